// round 12
// baseline (speedup 1.0000x reference)
#include <cuda_runtime.h>
#include <cuda_bf16.h>
#include <math.h>
#include <stdint.h>

#define BATCH 2
#define SEQ 2048
#define DM 1024
#define NH 16
#define HD 64

// ---------------- scratch (static device globals; no allocs allowed) ----------------
__device__ float g_cos[SEQ * (HD / 2)];
__device__ float g_sin[SEQ * (HD / 2)];

// split-bf16 Q/K/V, [b][h][s][hd]
__device__ __nv_bfloat16 g_Qh[(size_t)BATCH * NH * SEQ * HD];
__device__ __nv_bfloat16 g_Ql[(size_t)BATCH * NH * SEQ * HD];
__device__ __nv_bfloat16 g_Kh[(size_t)BATCH * NH * SEQ * HD];
__device__ __nv_bfloat16 g_Kl[(size_t)BATCH * NH * SEQ * HD];
__device__ __nv_bfloat16 g_Vh[(size_t)BATCH * NH * SEQ * HD];
__device__ __nv_bfloat16 g_Vl[(size_t)BATCH * NH * SEQ * HD];

// split-bf16 GEMM operand buffers (x for QKV projs; attention writes Ctx here)
__device__ __nv_bfloat16 g_Ah[(size_t)BATCH * SEQ * DM];
__device__ __nv_bfloat16 g_Al[(size_t)BATCH * SEQ * DM];
__device__ __nv_bfloat16 g_Wh[4][(size_t)DM * DM];       // weights hi: q,k,v,o
__device__ __nv_bfloat16 g_Wl[4][(size_t)DM * DM];       // weights lo

// ---------------- PTX helpers (generic-PTX-safe; sm_80-era features only) ---------
__device__ __forceinline__ uint32_t smem_u32(const void* p) {
    uint32_t a;
    asm("{ .reg .u64 t; cvta.to.shared.u64 t, %1; cvt.u32.u64 %0, t; }" : "=r"(a) : "l"(p));
    return a;
}

__device__ __forceinline__ void sts128(uint32_t addr, uint4 v) {
    asm volatile("st.shared.v4.b32 [%0], {%1,%2,%3,%4};"
                 :: "r"(addr), "r"(v.x), "r"(v.y), "r"(v.z), "r"(v.w) : "memory");
}

__device__ __forceinline__ void cpasync16(uint32_t dst, const void* src) {
    asm volatile("cp.async.cg.shared.global [%0], [%1], 16;" :: "r"(dst), "l"(src) : "memory");
}
__device__ __forceinline__ void cp_commit() {
    asm volatile("cp.async.commit_group;" ::: "memory");
}
template <int N>
__device__ __forceinline__ void cp_wait() {
    asm volatile("cp.async.wait_group %0;" :: "n"(N) : "memory");
}

__device__ __forceinline__ void ldsm4(uint32_t* r, uint32_t addr) {
    asm volatile("ldmatrix.sync.aligned.m8n8.x4.shared.b16 {%0,%1,%2,%3}, [%4];"
                 : "=r"(r[0]), "=r"(r[1]), "=r"(r[2]), "=r"(r[3]) : "r"(addr));
}

__device__ __forceinline__ void ldsm4t(uint32_t* r, uint32_t addr) {
    asm volatile("ldmatrix.sync.aligned.m8n8.x4.trans.shared.b16 {%0,%1,%2,%3}, [%4];"
                 : "=r"(r[0]), "=r"(r[1]), "=r"(r[2]), "=r"(r[3]) : "r"(addr));
}

__device__ __forceinline__ void mma16816(float* c, const uint32_t* a, uint32_t b0, uint32_t b1) {
    asm volatile(
        "mma.sync.aligned.m16n8k16.row.col.f32.bf16.bf16.f32 "
        "{%0,%1,%2,%3}, {%4,%5,%6,%7}, {%8,%9}, {%0,%1,%2,%3};"
        : "+f"(c[0]), "+f"(c[1]), "+f"(c[2]), "+f"(c[3])
        : "r"(a[0]), "r"(a[1]), "r"(a[2]), "r"(a[3]), "r"(b0), "r"(b1));
}

// split two fp32 -> packed bf16x2 hi + bf16x2 lo (element0 in low half)
__device__ __forceinline__ void split_pack(float a, float b, uint32_t& hi, uint32_t& lo) {
    __nv_bfloat16 ha = __float2bfloat16(a), hb = __float2bfloat16(b);
    __nv_bfloat16 la = __float2bfloat16(a - __bfloat162float(ha));
    __nv_bfloat16 lb = __float2bfloat16(b - __bfloat162float(hb));
    __nv_bfloat162 H; H.x = ha; H.y = hb;
    __nv_bfloat162 L; L.x = la; L.y = lb;
    hi = *(uint32_t*)&H;
    lo = *(uint32_t*)&L;
}

// swizzle for 64-byte rows (GEMM tiles)
__device__ __forceinline__ uint32_t sw64(uint32_t off) {
    return off ^ (((off >> 7) & 3u) << 4);
}
// swizzle for 128-byte rows (attention tiles)
__device__ __forceinline__ uint32_t sw128(uint32_t off) {
    return off ^ ((off >> 3) & 0x70u);
}

// ---------------- RoPE table ----------------
__global__ void rope_table_kernel() {
    int idx = blockIdx.x * blockDim.x + threadIdx.x;
    if (idx >= SEQ * (HD / 2)) return;
    int s = idx >> 5;          // HD/2 = 32
    int p = idx & 31;
    float freq = powf(10000.0f, -(float)(2 * p) / (float)HD);
    float ang = (float)s * freq;
    g_cos[idx] = cosf(ang);
    g_sin[idx] = sinf(ang);
}

// ---------------- fp32 -> bf16 hi/lo split (single tensor) ----------------
__global__ void split_kernel(const float* __restrict__ x,
                             __nv_bfloat16* __restrict__ hi,
                             __nv_bfloat16* __restrict__ lo, int n4) {
    int i = blockIdx.x * blockDim.x + threadIdx.x;
    if (i >= n4) return;
    float4 v = ((const float4*)x)[i];
    uint32_t h0, l0, h1, l1;
    split_pack(v.x, v.y, h0, l0);
    split_pack(v.z, v.w, h1, l1);
    ((uint32_t*)hi)[2 * i]     = h0;
    ((uint32_t*)hi)[2 * i + 1] = h1;
    ((uint32_t*)lo)[2 * i]     = l0;
    ((uint32_t*)lo)[2 * i + 1] = l1;
}

// all four weight matrices in one launch
__global__ void split4_kernel(const float* __restrict__ W0, const float* __restrict__ W1,
                              const float* __restrict__ W2, const float* __restrict__ W3,
                              __nv_bfloat16* __restrict__ hi, __nv_bfloat16* __restrict__ lo,
                              int n4) {
    int i = blockIdx.x * blockDim.x + threadIdx.x;
    if (i >= 4 * n4) return;
    const int w = i / n4;
    const int j = i - w * n4;
    const float* W = (w == 0) ? W0 : (w == 1) ? W1 : (w == 2) ? W2 : W3;
    float4 v = ((const float4*)W)[j];
    uint32_t h0, l0, h1, l1;
    split_pack(v.x, v.y, h0, l0);
    split_pack(v.z, v.w, h1, l1);
    const size_t base = (size_t)w * (DM * DM / 2);   // in uint32 units
    ((uint32_t*)hi)[base + 2 * j]     = h0;
    ((uint32_t*)hi)[base + 2 * j + 1] = h1;
    ((uint32_t*)lo)[base + 2 * j]     = l0;
    ((uint32_t*)lo)[base + 2 * j + 1] = l1;
}

// ---------------- HMMA split-bf16 GEMM, 3-stage cp.async, single-barrier pipeline ---
// C = A(MxK) @ B(NxK)^T. Block tile 128x128, 8 warps, warp tile 32x64, K-chunk 32.
// MODE 0: row-major fp32 C[M][N]  (O projection)
// MODE 3: fused QKV — blockIdx.z selects weight/output; z<2 applies RoPE.
template <int MODE>
__global__ void __launch_bounds__(256, 2) tgemm_kernel(const __nv_bfloat16* __restrict__ Ah,
                                                       const __nv_bfloat16* __restrict__ Al,
                                                       const __nv_bfloat16* __restrict__ Bh0,
                                                       const __nv_bfloat16* __restrict__ Bl0,
                                                       float* __restrict__ C,
                                                       __nv_bfloat16* __restrict__ Qh,
                                                       __nv_bfloat16* __restrict__ Ql,
                                                       __nv_bfloat16* __restrict__ Kh,
                                                       __nv_bfloat16* __restrict__ Kl,
                                                       __nv_bfloat16* __restrict__ Vh,
                                                       __nv_bfloat16* __restrict__ Vl)
{
    constexpr int Kdim = DM;
    constexpr int NCH = Kdim / 32;         // 32 K-chunks of 32
    extern __shared__ char smem[];
    const int tid = threadIdx.x;
    const int wid = tid >> 5;
    const int l   = tid & 31;
    const int bm = blockIdx.y * 128;
    const int bn = blockIdx.x * 128;

    const __nv_bfloat16* Bh = Bh0;
    const __nv_bfloat16* Bl = Bl0;
    if (MODE == 3) {
        const size_t woff = (size_t)blockIdx.z * DM * DM;
        Bh = Bh0 + woff;
        Bl = Bl0 + woff;
    }

    const uint32_t tb = (smem_u32(smem) + 127) & ~127u;
    // stage s at tb + s*32768; tiles Ah,Al,Bh,Bl at +0,+8192,+16384,+24576 (128 rows x 64B)

    const int wm = (wid >> 1) * 32;
    const int wn = (wid & 1) * 64;

    float acc[2][8][4];
#pragma unroll
    for (int mf = 0; mf < 2; mf++)
#pragma unroll
        for (int nf = 0; nf < 8; nf++)
#pragma unroll
            for (int q = 0; q < 4; q++) acc[mf][nf][q] = 0.0f;

    const int frow = (l & 7) + ((l >> 3) & 1) * 8;
    const int koff = ((l >> 4) & 1) * 8;

    // async-load one K-chunk (32 wide) into a stage
    auto load_chunk = [&](int c, int st) {
        const int k0 = c * 32;
        const uint32_t s0 = tb + st * 32768;
#pragma unroll
        for (int i = 0; i < 2; i++) {
            const int id = tid + i * 256;
            const int row = id >> 2;            // 0..127
            const int ch = id & 3;              // 0..3 (16B chunks)
            const uint32_t sw = sw64((uint32_t)row * 64 + ch * 16);
            const size_t ga = (size_t)(bm + row) * Kdim + k0 + ch * 8;
            const size_t gb = (size_t)(bn + row) * Kdim + k0 + ch * 8;
            cpasync16(s0 + sw,         Ah + ga);
            cpasync16(s0 + 8192 + sw,  Al + ga);
            cpasync16(s0 + 16384 + sw, Bh + gb);
            cpasync16(s0 + 24576 + sw, Bl + gb);
        }
        cp_commit();
    };

    load_chunk(0, 0);
    load_chunk(1, 1);

    for (int c = 0; c < NCH; c++) {
        if (c + 1 < NCH) cp_wait<1>(); else cp_wait<0>();
        __syncthreads();
        // prefetch into the stage consumed at iteration c-1 (safe: barrier above)
        if (c + 2 < NCH) load_chunk(c + 2, (c + 2) % 3);

        const uint32_t s0 = tb + (c % 3) * 32768;
        const uint32_t sAh = s0, sAl = s0 + 8192, sBh = s0 + 16384, sBl = s0 + 24576;

#pragma unroll
        for (int ks = 0; ks < 2; ks++) {
            const int kk = ks * 16 + koff;
            uint32_t ahf[2][4], alf[2][4];
#pragma unroll
            for (int mf = 0; mf < 2; mf++) {
                const uint32_t sw = sw64((uint32_t)(wm + mf * 16 + frow) * 64 + kk * 2);
                ldsm4(ahf[mf], sAh + sw);
                ldsm4(alf[mf], sAl + sw);
            }
#pragma unroll
            for (int np = 0; np < 4; np++) {
                const uint32_t sw = sw64((uint32_t)(wn + np * 16 + frow) * 64 + kk * 2);
                uint32_t bhf[4], blf[4];
                ldsm4(bhf, sBh + sw);
                ldsm4(blf, sBl + sw);
#pragma unroll
                for (int mf = 0; mf < 2; mf++) {
                    mma16816(acc[mf][np * 2 + 0], ahf[mf], bhf[0], bhf[2]);
                    mma16816(acc[mf][np * 2 + 0], ahf[mf], blf[0], blf[2]);
                    mma16816(acc[mf][np * 2 + 0], alf[mf], bhf[0], bhf[2]);
                    mma16816(acc[mf][np * 2 + 1], ahf[mf], bhf[1], bhf[3]);
                    mma16816(acc[mf][np * 2 + 1], ahf[mf], blf[1], blf[3]);
                    mma16816(acc[mf][np * 2 + 1], alf[mf], bhf[1], bhf[3]);
                }
            }
        }
    }

    __nv_bfloat16* Ch = nullptr;
    __nv_bfloat16* Cl = nullptr;
    bool rope = false;
    if (MODE == 3) {
        Ch = (blockIdx.z == 0) ? Qh : (blockIdx.z == 1) ? Kh : Vh;
        Cl = (blockIdx.z == 0) ? Ql : (blockIdx.z == 1) ? Kl : Vl;
        rope = (blockIdx.z < 2);
    }

    const int r_lane = l >> 2;
    const int c_lane = (l & 3) * 2;
#pragma unroll
    for (int mf = 0; mf < 2; mf++) {
#pragma unroll
        for (int half = 0; half < 2; half++) {
            const int mrow = bm + wm + mf * 16 + r_lane + half * 8;
            const int b = mrow >> 11;            // SEQ = 2048
            const int s = mrow & (SEQ - 1);
#pragma unroll
            for (int nf = 0; nf < 8; nf++) {
                float e = acc[mf][nf][half * 2 + 0];
                float o = acc[mf][nf][half * 2 + 1];
                const int col = bn + wn + nf * 8 + c_lane;   // even
                if (MODE == 0) {
                    float2 v; v.x = e; v.y = o;
                    *(float2*)(C + (size_t)mrow * DM + col) = v;
                } else {
                    const int h = col >> 6;
                    const int d0 = col & 63;
                    if (rope) {
                        const int p = d0 >> 1;
                        const float cs = g_cos[s * 32 + p];
                        const float sn = g_sin[s * 32 + p];
                        const float re = e * cs - o * sn;
                        const float ro = e * sn + o * cs;
                        e = re; o = ro;
                    }
                    const size_t idx = (((size_t)b * NH + h) * SEQ + s) * HD + d0;
                    uint32_t hi, lo;
                    split_pack(e, o, hi, lo);
                    *(uint32_t*)(Ch + idx) = hi;
                    *(uint32_t*)(Cl + idx) = lo;
                }
            }
        }
    }
}

// ---------------- HMMA flash attention (split-bf16, causal, 128-row Q blocks) ------
// grid (SEQ/128, BATCH*NH), 256 threads = 8 warps x 16 query rows.
// Longest blocks first; lower-half warps skip fully-masked diagonal tiles.
__global__ void __launch_bounds__(256, 2) attn_hmma_kernel(__nv_bfloat16* __restrict__ Oh,
                                                           __nv_bfloat16* __restrict__ Ol)
{
    const int qb2 = (int)gridDim.x - 1 - (int)blockIdx.x;   // longest-first
    const int bh = blockIdx.y;
    const int b  = bh >> 4;
    const int h  = bh & 15;
    const size_t base = (size_t)bh * SEQ * HD;

    extern __shared__ char smem[];
    const uint32_t tb  = (smem_u32(smem) + 127) & ~127u;
    const uint32_t sQh = tb;                 // 128 rows x 128B = 16KB
    const uint32_t sQl = tb + 16384;
    const uint32_t kvb = tb + 32768;         // stage s: kvb + s*32768; Kh,Kl,Vh,Vl at +0,8192,16384,24576

    const int tid = threadIdx.x;
    const int wid = tid >> 5;                // 0..7
    const int l   = tid & 31;
    const int wm  = wid * 16;                // warp's q-row offset within 128-row block
    const int frow = (l & 7) + ((l >> 3) & 1) * 8;
    const int koff = ((l >> 4) & 1) * 8;
    const int r  = l >> 2;
    const int cj = (l & 3) * 2;

    auto load_kv = [&](int jb, int st) {
        const uint32_t s0 = kvb + st * 32768;
#pragma unroll
        for (int i = 0; i < 2; i++) {
            const int id = tid + i * 256;
            const int row = id >> 3;           // 0..63
            const int ch = id & 7;
            const uint32_t sw = sw128((uint32_t)row * 128 + ch * 16);
            const size_t g = base + (size_t)(jb * 64 + row) * HD + ch * 8;
            cpasync16(s0 + sw,         g_Kh + g);
            cpasync16(s0 + 8192 + sw,  g_Kl + g);
            cpasync16(s0 + 16384 + sw, g_Vh + g);
            cpasync16(s0 + 24576 + sw, g_Vl + g);
        }
        cp_commit();
    };

    load_kv(0, 0);

    // load Q block (128 x 64 bf16, hi+lo) swizzled
#pragma unroll
    for (int i = 0; i < 4; i++) {
        const int id = tid + i * 256;
        const int row = id >> 3;               // 0..127
        const int ch = id & 7;
        const uint32_t sw = sw128((uint32_t)row * 128 + ch * 16);
        const size_t g = base + (size_t)(qb2 * 128 + row) * HD + ch * 8;
        sts128(sQh + sw, *(const uint4*)(g_Qh + g));
        sts128(sQl + sw, *(const uint4*)(g_Ql + g));
    }
    __syncthreads();

    // preload Q fragments (16 rows x 64 k)
    uint32_t qh[4][4], ql[4][4];
#pragma unroll
    for (int ks = 0; ks < 4; ks++) {
        const uint32_t sw = sw128((uint32_t)(wm + frow) * 128 + (ks * 16 + koff) * 2);
        ldsm4(qh[ks], sQh + sw);
        ldsm4(ql[ks], sQl + sw);
    }

    float m0 = -1e30f, m1 = -1e30f, l0 = 0.0f, l1 = 0.0f;
    float o[8][4];
#pragma unroll
    for (int nf = 0; nf < 8; nf++)
#pragma unroll
        for (int q = 0; q < 4; q++) o[nf][q] = 0.0f;

    const int qmin = qb2 * 128 + wm;           // warp's first global q row
    const int jmax = 2 * qb2 + 1;

    for (int jb = 0; jb <= jmax; jb++) {
        cp_wait<0>();
        __syncthreads();
        if (jb < jmax) load_kv(jb + 1, (jb + 1) & 1);   // overlaps compute below

        // warp-level skip: tile entirely above the diagonal for this warp's rows
        if (jb * 64 > qmin + 15) continue;

        const uint32_t s0 = kvb + (jb & 1) * 32768;
        const uint32_t sKh = s0, sKl = s0 + 8192, sVh = s0 + 16384, sVl = s0 + 24576;

        // S = Q @ K^T (split 3-MMA), 16x64 per warp
        float sv[8][4];
#pragma unroll
        for (int nf = 0; nf < 8; nf++)
#pragma unroll
            for (int q = 0; q < 4; q++) sv[nf][q] = 0.0f;

#pragma unroll
        for (int np = 0; np < 4; np++) {
#pragma unroll
            for (int ks = 0; ks < 4; ks++) {
                const uint32_t sw = sw128((uint32_t)(np * 16 + frow) * 128 + (ks * 16 + koff) * 2);
                uint32_t khf[4], klf[4];
                ldsm4(khf, sKh + sw);
                ldsm4(klf, sKl + sw);
                mma16816(sv[np * 2 + 0], qh[ks], khf[0], khf[2]);
                mma16816(sv[np * 2 + 0], qh[ks], klf[0], klf[2]);
                mma16816(sv[np * 2 + 0], ql[ks], khf[0], khf[2]);
                mma16816(sv[np * 2 + 1], qh[ks], khf[1], khf[3]);
                mma16816(sv[np * 2 + 1], qh[ks], klf[1], klf[3]);
                mma16816(sv[np * 2 + 1], ql[ks], khf[1], khf[3]);
            }
        }

        // scale + causal mask (only when tile touches the diagonal for this warp)
#pragma unroll
        for (int nf = 0; nf < 8; nf++)
#pragma unroll
            for (int q = 0; q < 4; q++) sv[nf][q] *= 0.125f;

        if (jb * 64 + 63 > qmin) {
            const int q0g = qmin + r;
#pragma unroll
            for (int nf = 0; nf < 8; nf++) {
                const int k0g = jb * 64 + nf * 8 + cj;
                if (k0g     > q0g)     sv[nf][0] = -1e30f;
                if (k0g + 1 > q0g)     sv[nf][1] = -1e30f;
                if (k0g     > q0g + 8) sv[nf][2] = -1e30f;
                if (k0g + 1 > q0g + 8) sv[nf][3] = -1e30f;
            }
        }

        // online softmax, rows r (regs 0,1) and r+8 (regs 2,3)
        float mt0 = -1e30f, mt1 = -1e30f;
#pragma unroll
        for (int nf = 0; nf < 8; nf++) {
            mt0 = fmaxf(mt0, fmaxf(sv[nf][0], sv[nf][1]));
            mt1 = fmaxf(mt1, fmaxf(sv[nf][2], sv[nf][3]));
        }
        mt0 = fmaxf(mt0, __shfl_xor_sync(0xffffffffu, mt0, 1));
        mt0 = fmaxf(mt0, __shfl_xor_sync(0xffffffffu, mt0, 2));
        mt1 = fmaxf(mt1, __shfl_xor_sync(0xffffffffu, mt1, 1));
        mt1 = fmaxf(mt1, __shfl_xor_sync(0xffffffffu, mt1, 2));
        const float mn0 = fmaxf(m0, mt0);
        const float mn1 = fmaxf(m1, mt1);

        float ls0 = 0.0f, ls1 = 0.0f;
#pragma unroll
        for (int nf = 0; nf < 8; nf++) {
            sv[nf][0] = __expf(sv[nf][0] - mn0);
            sv[nf][1] = __expf(sv[nf][1] - mn0);
            sv[nf][2] = __expf(sv[nf][2] - mn1);
            sv[nf][3] = __expf(sv[nf][3] - mn1);
            ls0 += sv[nf][0] + sv[nf][1];
            ls1 += sv[nf][2] + sv[nf][3];
        }
        ls0 += __shfl_xor_sync(0xffffffffu, ls0, 1);
        ls0 += __shfl_xor_sync(0xffffffffu, ls0, 2);
        ls1 += __shfl_xor_sync(0xffffffffu, ls1, 1);
        ls1 += __shfl_xor_sync(0xffffffffu, ls1, 2);

        const float a0 = __expf(m0 - mn0);
        const float a1 = __expf(m1 - mn1);
        l0 = l0 * a0 + ls0;
        l1 = l1 * a1 + ls1;
        m0 = mn0; m1 = mn1;
#pragma unroll
        for (int nf = 0; nf < 8; nf++) {
            o[nf][0] *= a0; o[nf][1] *= a0;
            o[nf][2] *= a1; o[nf][3] *= a1;
        }

        // O += P @ V (split 3-MMA), P fragments straight from accumulators
#pragma unroll
        for (int kp = 0; kp < 4; kp++) {
            uint32_t Ph[4], Pl[4];
            split_pack(sv[2 * kp][0],     sv[2 * kp][1],     Ph[0], Pl[0]);
            split_pack(sv[2 * kp][2],     sv[2 * kp][3],     Ph[1], Pl[1]);
            split_pack(sv[2 * kp + 1][0], sv[2 * kp + 1][1], Ph[2], Pl[2]);
            split_pack(sv[2 * kp + 1][2], sv[2 * kp + 1][3], Ph[3], Pl[3]);
#pragma unroll
            for (int hp = 0; hp < 4; hp++) {
                const uint32_t sw = sw128((uint32_t)(kp * 16 + frow) * 128 + (hp * 16 + koff) * 2);
                uint32_t vhf[4], vlf[4];
                ldsm4t(vhf, sVh + sw);
                ldsm4t(vlf, sVl + sw);
                mma16816(o[hp * 2 + 0], Ph, vhf[0], vhf[1]);
                mma16816(o[hp * 2 + 0], Ph, vlf[0], vlf[1]);
                mma16816(o[hp * 2 + 0], Pl, vhf[0], vhf[1]);
                mma16816(o[hp * 2 + 1], Ph, vhf[2], vhf[3]);
                mma16816(o[hp * 2 + 1], Ph, vlf[2], vlf[3]);
                mma16816(o[hp * 2 + 1], Pl, vhf[2], vhf[3]);
            }
        }
    }

    // epilogue: normalize, split-bf16 scatter to concat [b][s][d]
    const float inv0 = 1.0f / l0;
    const float inv1 = 1.0f / l1;
    const int q0 = qb2 * 128 + wm + r;
    const int q1 = q0 + 8;
#pragma unroll
    for (int nf = 0; nf < 8; nf++) {
        const int col = h * HD + nf * 8 + cj;
        uint32_t hi, lo;
        split_pack(o[nf][0] * inv0, o[nf][1] * inv0, hi, lo);
        const size_t i0 = ((size_t)b * SEQ + q0) * DM + col;
        *(uint32_t*)(Oh + i0) = hi;
        *(uint32_t*)(Ol + i0) = lo;
        split_pack(o[nf][2] * inv1, o[nf][3] * inv1, hi, lo);
        const size_t i1 = ((size_t)b * SEQ + q1) * DM + col;
        *(uint32_t*)(Oh + i1) = hi;
        *(uint32_t*)(Ol + i1) = lo;
    }
}

// ---------------- launch ----------------
extern "C" void kernel_launch(void* const* d_in, const int* in_sizes, int n_in,
                              void* d_out, int out_size)
{
    const float* x  = (const float*)d_in[0];
    const float* Wq = (const float*)d_in[1];
    const float* Wk = (const float*)d_in[2];
    const float* Wv = (const float*)d_in[3];
    const float* Wo = (const float*)d_in[4];
    float* out = (float*)d_out;

    __nv_bfloat16 *pAh, *pAl, *pWh, *pWl, *pQh, *pQl, *pKh, *pKl, *pVh, *pVl;
    cudaGetSymbolAddress((void**)&pAh, g_Ah);
    cudaGetSymbolAddress((void**)&pAl, g_Al);
    cudaGetSymbolAddress((void**)&pWh, g_Wh);
    cudaGetSymbolAddress((void**)&pWl, g_Wl);
    cudaGetSymbolAddress((void**)&pQh, g_Qh);
    cudaGetSymbolAddress((void**)&pQl, g_Ql);
    cudaGetSymbolAddress((void**)&pKh, g_Kh);
    cudaGetSymbolAddress((void**)&pKl, g_Kl);
    cudaGetSymbolAddress((void**)&pVh, g_Vh);
    cudaGetSymbolAddress((void**)&pVl, g_Vl);

    const int GSMEM = 3 * 32768 + 256;          // 3-stage, K-chunk 32 -> 2 CTAs/SM
    cudaFuncSetAttribute(tgemm_kernel<0>, cudaFuncAttributeMaxDynamicSharedMemorySize, GSMEM);
    cudaFuncSetAttribute(tgemm_kernel<3>, cudaFuncAttributeMaxDynamicSharedMemorySize, GSMEM);

    rope_table_kernel<<<(SEQ * 32 + 255) / 256, 256>>>();

    const int nx4 = BATCH * SEQ * DM / 4;
    const int nw4 = DM * DM / 4;
    split_kernel<<<(nx4 + 255) / 256, 256>>>(x, pAh, pAl, nx4);
    split4_kernel<<<(4 * nw4 + 255) / 256, 256>>>(Wq, Wk, Wv, Wo, pWh, pWl, nw4);

    // fused QKV projections: grid.z selects weight + output
    dim3 qkvgrid(DM / 128, BATCH * SEQ / 128, 3);   // (8, 32, 3)
    tgemm_kernel<3><<<qkvgrid, 256, GSMEM>>>(pAh, pAl, pWh, pWl,
                                             nullptr, pQh, pQl, pKh, pKl, pVh, pVl);

    const int ASMEM = 32768 + 2 * 32768 + 256;  // Q(128 rows) + double-buffered KV
    cudaFuncSetAttribute(attn_hmma_kernel, cudaFuncAttributeMaxDynamicSharedMemorySize, ASMEM);
    attn_hmma_kernel<<<dim3(SEQ / 128, BATCH * NH), 256, ASMEM>>>(pAh, pAl);

    dim3 ogrid(DM / 128, BATCH * SEQ / 128);
    tgemm_kernel<0><<<ogrid, 256, GSMEM>>>(pAh, pAl, pWh + 3 * (size_t)DM * DM, pWl + 3 * (size_t)DM * DM,
                                           out, nullptr, nullptr, nullptr, nullptr, nullptr, nullptr);
}

// round 13
// speedup vs baseline: 1.0972x; 1.0972x over previous
#include <cuda_runtime.h>
#include <cuda_bf16.h>
#include <math.h>
#include <stdint.h>

#define BATCH 2
#define SEQ 2048
#define DM 1024
#define NH 16
#define HD 64

// ---------------- scratch (static device globals; no allocs allowed) ----------------
__device__ float g_cos[SEQ * (HD / 2)];
__device__ float g_sin[SEQ * (HD / 2)];

// split-bf16 Q/K/V, [b][h][s][hd]
__device__ __nv_bfloat16 g_Qh[(size_t)BATCH * NH * SEQ * HD];
__device__ __nv_bfloat16 g_Ql[(size_t)BATCH * NH * SEQ * HD];
__device__ __nv_bfloat16 g_Kh[(size_t)BATCH * NH * SEQ * HD];
__device__ __nv_bfloat16 g_Kl[(size_t)BATCH * NH * SEQ * HD];
__device__ __nv_bfloat16 g_Vh[(size_t)BATCH * NH * SEQ * HD];
__device__ __nv_bfloat16 g_Vl[(size_t)BATCH * NH * SEQ * HD];

// split-bf16 GEMM operand buffers (x for QKV projs; attention writes Ctx here)
__device__ __nv_bfloat16 g_Ah[(size_t)BATCH * SEQ * DM];
__device__ __nv_bfloat16 g_Al[(size_t)BATCH * SEQ * DM];
__device__ __nv_bfloat16 g_Wh[4][(size_t)DM * DM];       // weights hi: q,k,v,o
__device__ __nv_bfloat16 g_Wl[4][(size_t)DM * DM];       // weights lo

// ---------------- PTX helpers (generic-PTX-safe; sm_80-era features only) ---------
__device__ __forceinline__ uint32_t smem_u32(const void* p) {
    uint32_t a;
    asm("{ .reg .u64 t; cvta.to.shared.u64 t, %1; cvt.u32.u64 %0, t; }" : "=r"(a) : "l"(p));
    return a;
}

__device__ __forceinline__ void sts128(uint32_t addr, uint4 v) {
    asm volatile("st.shared.v4.b32 [%0], {%1,%2,%3,%4};"
                 :: "r"(addr), "r"(v.x), "r"(v.y), "r"(v.z), "r"(v.w) : "memory");
}

__device__ __forceinline__ void cpasync16(uint32_t dst, const void* src) {
    asm volatile("cp.async.cg.shared.global [%0], [%1], 16;" :: "r"(dst), "l"(src) : "memory");
}
__device__ __forceinline__ void cp_commit() {
    asm volatile("cp.async.commit_group;" ::: "memory");
}
template <int N>
__device__ __forceinline__ void cp_wait() {
    asm volatile("cp.async.wait_group %0;" :: "n"(N) : "memory");
}

__device__ __forceinline__ void ldsm4(uint32_t* r, uint32_t addr) {
    asm volatile("ldmatrix.sync.aligned.m8n8.x4.shared.b16 {%0,%1,%2,%3}, [%4];"
                 : "=r"(r[0]), "=r"(r[1]), "=r"(r[2]), "=r"(r[3]) : "r"(addr));
}

__device__ __forceinline__ void ldsm4t(uint32_t* r, uint32_t addr) {
    asm volatile("ldmatrix.sync.aligned.m8n8.x4.trans.shared.b16 {%0,%1,%2,%3}, [%4];"
                 : "=r"(r[0]), "=r"(r[1]), "=r"(r[2]), "=r"(r[3]) : "r"(addr));
}

__device__ __forceinline__ void mma16816(float* c, const uint32_t* a, uint32_t b0, uint32_t b1) {
    asm volatile(
        "mma.sync.aligned.m16n8k16.row.col.f32.bf16.bf16.f32 "
        "{%0,%1,%2,%3}, {%4,%5,%6,%7}, {%8,%9}, {%0,%1,%2,%3};"
        : "+f"(c[0]), "+f"(c[1]), "+f"(c[2]), "+f"(c[3])
        : "r"(a[0]), "r"(a[1]), "r"(a[2]), "r"(a[3]), "r"(b0), "r"(b1));
}

// split two fp32 -> packed bf16x2 hi + bf16x2 lo (element0 in low half)
__device__ __forceinline__ void split_pack(float a, float b, uint32_t& hi, uint32_t& lo) {
    __nv_bfloat16 ha = __float2bfloat16(a), hb = __float2bfloat16(b);
    __nv_bfloat16 la = __float2bfloat16(a - __bfloat162float(ha));
    __nv_bfloat16 lb = __float2bfloat16(b - __bfloat162float(hb));
    __nv_bfloat162 H; H.x = ha; H.y = hb;
    __nv_bfloat162 L; L.x = la; L.y = lb;
    hi = *(uint32_t*)&H;
    lo = *(uint32_t*)&L;
}

// swizzle for 64-byte rows (GEMM tiles)
__device__ __forceinline__ uint32_t sw64(uint32_t off) {
    return off ^ (((off >> 7) & 3u) << 4);
}
// swizzle for 128-byte rows (attention tiles)
__device__ __forceinline__ uint32_t sw128(uint32_t off) {
    return off ^ ((off >> 3) & 0x70u);
}

// ---------------- RoPE table ----------------
__global__ void rope_table_kernel() {
    int idx = blockIdx.x * blockDim.x + threadIdx.x;
    if (idx >= SEQ * (HD / 2)) return;
    int s = idx >> 5;          // HD/2 = 32
    int p = idx & 31;
    float freq = powf(10000.0f, -(float)(2 * p) / (float)HD);
    float ang = (float)s * freq;
    g_cos[idx] = cosf(ang);
    g_sin[idx] = sinf(ang);
}

// ---------------- fp32 -> bf16 hi/lo split (single tensor) ----------------
__global__ void split_kernel(const float* __restrict__ x,
                             __nv_bfloat16* __restrict__ hi,
                             __nv_bfloat16* __restrict__ lo, int n4) {
    int i = blockIdx.x * blockDim.x + threadIdx.x;
    if (i >= n4) return;
    float4 v = ((const float4*)x)[i];
    uint32_t h0, l0, h1, l1;
    split_pack(v.x, v.y, h0, l0);
    split_pack(v.z, v.w, h1, l1);
    ((uint32_t*)hi)[2 * i]     = h0;
    ((uint32_t*)hi)[2 * i + 1] = h1;
    ((uint32_t*)lo)[2 * i]     = l0;
    ((uint32_t*)lo)[2 * i + 1] = l1;
}

// all four weight matrices in one launch
__global__ void split4_kernel(const float* __restrict__ W0, const float* __restrict__ W1,
                              const float* __restrict__ W2, const float* __restrict__ W3,
                              __nv_bfloat16* __restrict__ hi, __nv_bfloat16* __restrict__ lo,
                              int n4) {
    int i = blockIdx.x * blockDim.x + threadIdx.x;
    if (i >= 4 * n4) return;
    const int w = i / n4;
    const int j = i - w * n4;
    const float* W = (w == 0) ? W0 : (w == 1) ? W1 : (w == 2) ? W2 : W3;
    float4 v = ((const float4*)W)[j];
    uint32_t h0, l0, h1, l1;
    split_pack(v.x, v.y, h0, l0);
    split_pack(v.z, v.w, h1, l1);
    const size_t base = (size_t)w * (DM * DM / 2);   // in uint32 units
    ((uint32_t*)hi)[base + 2 * j]     = h0;
    ((uint32_t*)hi)[base + 2 * j + 1] = h1;
    ((uint32_t*)lo)[base + 2 * j]     = l0;
    ((uint32_t*)lo)[base + 2 * j + 1] = l1;
}

// ---------------- HMMA split-bf16 GEMM, 3-stage cp.async, single-barrier pipeline ---
// C = A(MxK) @ B(NxK)^T. Block tile 128x128, 8 warps, warp tile 32x64, K-chunk 32.
// A-fragments for both ks-steps hoisted to chunk top (deeper LDSM window).
// MODE 0: row-major fp32 C[M][N]  (O projection)
// MODE 3: fused QKV — blockIdx.z selects weight/output; z<2 applies RoPE.
template <int MODE>
__global__ void __launch_bounds__(256, 2) tgemm_kernel(const __nv_bfloat16* __restrict__ Ah,
                                                       const __nv_bfloat16* __restrict__ Al,
                                                       const __nv_bfloat16* __restrict__ Bh0,
                                                       const __nv_bfloat16* __restrict__ Bl0,
                                                       float* __restrict__ C,
                                                       __nv_bfloat16* __restrict__ Qh,
                                                       __nv_bfloat16* __restrict__ Ql,
                                                       __nv_bfloat16* __restrict__ Kh,
                                                       __nv_bfloat16* __restrict__ Kl,
                                                       __nv_bfloat16* __restrict__ Vh,
                                                       __nv_bfloat16* __restrict__ Vl)
{
    constexpr int Kdim = DM;
    constexpr int NCH = Kdim / 32;         // 32 K-chunks of 32
    extern __shared__ char smem[];
    const int tid = threadIdx.x;
    const int wid = tid >> 5;
    const int l   = tid & 31;
    const int bm = blockIdx.y * 128;
    const int bn = blockIdx.x * 128;

    const __nv_bfloat16* Bh = Bh0;
    const __nv_bfloat16* Bl = Bl0;
    if (MODE == 3) {
        const size_t woff = (size_t)blockIdx.z * DM * DM;
        Bh = Bh0 + woff;
        Bl = Bl0 + woff;
    }

    const uint32_t tb = (smem_u32(smem) + 127) & ~127u;
    // stage s at tb + s*32768; tiles Ah,Al,Bh,Bl at +0,+8192,+16384,+24576 (128 rows x 64B)

    const int wm = (wid >> 1) * 32;
    const int wn = (wid & 1) * 64;

    float acc[2][8][4];
#pragma unroll
    for (int mf = 0; mf < 2; mf++)
#pragma unroll
        for (int nf = 0; nf < 8; nf++)
#pragma unroll
            for (int q = 0; q < 4; q++) acc[mf][nf][q] = 0.0f;

    const int frow = (l & 7) + ((l >> 3) & 1) * 8;
    const int koff = ((l >> 4) & 1) * 8;

    // async-load one K-chunk (32 wide) into a stage
    auto load_chunk = [&](int c, int st) {
        const int k0 = c * 32;
        const uint32_t s0 = tb + st * 32768;
#pragma unroll
        for (int i = 0; i < 2; i++) {
            const int id = tid + i * 256;
            const int row = id >> 2;            // 0..127
            const int ch = id & 3;              // 0..3 (16B chunks)
            const uint32_t sw = sw64((uint32_t)row * 64 + ch * 16);
            const size_t ga = (size_t)(bm + row) * Kdim + k0 + ch * 8;
            const size_t gb = (size_t)(bn + row) * Kdim + k0 + ch * 8;
            cpasync16(s0 + sw,         Ah + ga);
            cpasync16(s0 + 8192 + sw,  Al + ga);
            cpasync16(s0 + 16384 + sw, Bh + gb);
            cpasync16(s0 + 24576 + sw, Bl + gb);
        }
        cp_commit();
    };

    load_chunk(0, 0);
    load_chunk(1, 1);

    for (int c = 0; c < NCH; c++) {
        if (c + 1 < NCH) cp_wait<1>(); else cp_wait<0>();
        __syncthreads();
        // prefetch into the stage consumed at iteration c-1 (safe: barrier above)
        if (c + 2 < NCH) load_chunk(c + 2, (c + 2) % 3);

        const uint32_t s0 = tb + (c % 3) * 32768;
        const uint32_t sAh = s0, sAl = s0 + 8192, sBh = s0 + 16384, sBl = s0 + 24576;

        // hoist A fragments for both ks-steps: 8 independent LDSMs up front
        uint32_t ahf[2][2][4], alf[2][2][4];   // [ks][mf]
#pragma unroll
        for (int ks = 0; ks < 2; ks++) {
            const int kk = ks * 16 + koff;
#pragma unroll
            for (int mf = 0; mf < 2; mf++) {
                const uint32_t sw = sw64((uint32_t)(wm + mf * 16 + frow) * 64 + kk * 2);
                ldsm4(ahf[ks][mf], sAh + sw);
                ldsm4(alf[ks][mf], sAl + sw);
            }
        }

#pragma unroll
        for (int ks = 0; ks < 2; ks++) {
            const int kk = ks * 16 + koff;
#pragma unroll
            for (int np = 0; np < 4; np++) {
                const uint32_t sw = sw64((uint32_t)(wn + np * 16 + frow) * 64 + kk * 2);
                uint32_t bhf[4], blf[4];
                ldsm4(bhf, sBh + sw);
                ldsm4(blf, sBl + sw);
#pragma unroll
                for (int mf = 0; mf < 2; mf++) {
                    mma16816(acc[mf][np * 2 + 0], ahf[ks][mf], bhf[0], bhf[2]);
                    mma16816(acc[mf][np * 2 + 0], ahf[ks][mf], blf[0], blf[2]);
                    mma16816(acc[mf][np * 2 + 0], alf[ks][mf], bhf[0], bhf[2]);
                    mma16816(acc[mf][np * 2 + 1], ahf[ks][mf], bhf[1], bhf[3]);
                    mma16816(acc[mf][np * 2 + 1], ahf[ks][mf], blf[1], blf[3]);
                    mma16816(acc[mf][np * 2 + 1], alf[ks][mf], bhf[1], bhf[3]);
                }
            }
        }
    }

    __nv_bfloat16* Ch = nullptr;
    __nv_bfloat16* Cl = nullptr;
    bool rope = false;
    if (MODE == 3) {
        Ch = (blockIdx.z == 0) ? Qh : (blockIdx.z == 1) ? Kh : Vh;
        Cl = (blockIdx.z == 0) ? Ql : (blockIdx.z == 1) ? Kl : Vl;
        rope = (blockIdx.z < 2);
    }

    const int r_lane = l >> 2;
    const int c_lane = (l & 3) * 2;
#pragma unroll
    for (int mf = 0; mf < 2; mf++) {
#pragma unroll
        for (int half = 0; half < 2; half++) {
            const int mrow = bm + wm + mf * 16 + r_lane + half * 8;
            const int b = mrow >> 11;            // SEQ = 2048
            const int s = mrow & (SEQ - 1);
#pragma unroll
            for (int nf = 0; nf < 8; nf++) {
                float e = acc[mf][nf][half * 2 + 0];
                float o = acc[mf][nf][half * 2 + 1];
                const int col = bn + wn + nf * 8 + c_lane;   // even
                if (MODE == 0) {
                    float2 v; v.x = e; v.y = o;
                    *(float2*)(C + (size_t)mrow * DM + col) = v;
                } else {
                    const int h = col >> 6;
                    const int d0 = col & 63;
                    if (rope) {
                        const int p = d0 >> 1;
                        const float cs = g_cos[s * 32 + p];
                        const float sn = g_sin[s * 32 + p];
                        const float re = e * cs - o * sn;
                        const float ro = e * sn + o * cs;
                        e = re; o = ro;
                    }
                    const size_t idx = (((size_t)b * NH + h) * SEQ + s) * HD + d0;
                    uint32_t hi, lo;
                    split_pack(e, o, hi, lo);
                    *(uint32_t*)(Ch + idx) = hi;
                    *(uint32_t*)(Cl + idx) = lo;
                }
            }
        }
    }
}

// ---------------- HMMA flash attention (split-bf16, causal, cp.async pipelined) ----
// grid (SEQ/64, BATCH*NH), 128 threads = 4 warps x 16 query rows.
// R9-proven version: no launch_bounds min-blocks (needs ~160 regs, must not spill).
__global__ void __launch_bounds__(128) attn_hmma_kernel(__nv_bfloat16* __restrict__ Oh,
                                                        __nv_bfloat16* __restrict__ Ol)
{
    const int qb = (int)gridDim.x - 1 - (int)blockIdx.x;   // longest-first scheduling
    const int bh = blockIdx.y;
    const int b  = bh >> 4;
    const int h  = bh & 15;
    const size_t base = (size_t)bh * SEQ * HD;

    extern __shared__ char smem[];
    const uint32_t tb  = (smem_u32(smem) + 127) & ~127u;
    const uint32_t sQh = tb;
    const uint32_t sQl = tb + 8192;
    const uint32_t kvb = tb + 16384;   // stage s: kvb + s*32768; Kh,Kl,Vh,Vl at +0,8192,16384,24576

    const int tid = threadIdx.x;
    const int wid = tid >> 5;
    const int l   = tid & 31;
    const int wm  = wid * 16;
    const int frow = (l & 7) + ((l >> 3) & 1) * 8;
    const int koff = ((l >> 4) & 1) * 8;
    const int r  = l >> 2;
    const int cj = (l & 3) * 2;

    auto load_kv = [&](int jb, int st) {
        const uint32_t s0 = kvb + st * 32768;
#pragma unroll
        for (int i = 0; i < 4; i++) {
            const int id = tid + i * 128;
            const int row = id >> 3;
            const int ch = id & 7;
            const uint32_t sw = sw128((uint32_t)row * 128 + ch * 16);
            const size_t g = base + (size_t)(jb * 64 + row) * HD + ch * 8;
            cpasync16(s0 + sw,         g_Kh + g);
            cpasync16(s0 + 8192 + sw,  g_Kl + g);
            cpasync16(s0 + 16384 + sw, g_Vh + g);
            cpasync16(s0 + 24576 + sw, g_Vl + g);
        }
        cp_commit();
    };

    load_kv(0, 0);

    // load Q tile (64 x 64 bf16, hi+lo) swizzled
#pragma unroll
    for (int i = 0; i < 4; i++) {
        const int id = tid + i * 128;
        const int row = id >> 3;
        const int ch = id & 7;
        const uint32_t sw = sw128((uint32_t)row * 128 + ch * 16);
        const size_t g = base + (size_t)(qb * 64 + row) * HD + ch * 8;
        sts128(sQh + sw, *(const uint4*)(g_Qh + g));
        sts128(sQl + sw, *(const uint4*)(g_Ql + g));
    }
    __syncthreads();

    // preload Q fragments (16 rows x 64 k)
    uint32_t qh[4][4], ql[4][4];
#pragma unroll
    for (int ks = 0; ks < 4; ks++) {
        const uint32_t sw = sw128((uint32_t)(wm + frow) * 128 + (ks * 16 + koff) * 2);
        ldsm4(qh[ks], sQh + sw);
        ldsm4(ql[ks], sQl + sw);
    }

    float m0 = -1e30f, m1 = -1e30f, l0 = 0.0f, l1 = 0.0f;
    float o[8][4];
#pragma unroll
    for (int nf = 0; nf < 8; nf++)
#pragma unroll
        for (int q = 0; q < 4; q++) o[nf][q] = 0.0f;

    for (int jb = 0; jb <= qb; jb++) {
        if (jb + 1 <= qb) {
            load_kv(jb + 1, (jb + 1) & 1);
            cp_wait<1>();
        } else {
            cp_wait<0>();
        }
        __syncthreads();

        const uint32_t s0 = kvb + (jb & 1) * 32768;
        const uint32_t sKh = s0, sKl = s0 + 8192, sVh = s0 + 16384, sVl = s0 + 24576;

        // S = Q @ K^T (split 3-MMA), 16x64 per warp
        float sv[8][4];
#pragma unroll
        for (int nf = 0; nf < 8; nf++)
#pragma unroll
            for (int q = 0; q < 4; q++) sv[nf][q] = 0.0f;

#pragma unroll
        for (int np = 0; np < 4; np++) {
#pragma unroll
            for (int ks = 0; ks < 4; ks++) {
                const uint32_t sw = sw128((uint32_t)(np * 16 + frow) * 128 + (ks * 16 + koff) * 2);
                uint32_t khf[4], klf[4];
                ldsm4(khf, sKh + sw);
                ldsm4(klf, sKl + sw);
                mma16816(sv[np * 2 + 0], qh[ks], khf[0], khf[2]);
                mma16816(sv[np * 2 + 0], qh[ks], klf[0], klf[2]);
                mma16816(sv[np * 2 + 0], ql[ks], khf[0], khf[2]);
                mma16816(sv[np * 2 + 1], qh[ks], khf[1], khf[3]);
                mma16816(sv[np * 2 + 1], qh[ks], klf[1], klf[3]);
                mma16816(sv[np * 2 + 1], ql[ks], khf[1], khf[3]);
            }
        }

        // scale + causal mask (diagonal tile only)
#pragma unroll
        for (int nf = 0; nf < 8; nf++)
#pragma unroll
            for (int q = 0; q < 4; q++) sv[nf][q] *= 0.125f;

        if (jb == qb) {
#pragma unroll
            for (int nf = 0; nf < 8; nf++) {
                const int k0 = nf * 8 + cj;
                const int q0 = wm + r;
                if (k0     > q0)     sv[nf][0] = -1e30f;
                if (k0 + 1 > q0)     sv[nf][1] = -1e30f;
                if (k0     > q0 + 8) sv[nf][2] = -1e30f;
                if (k0 + 1 > q0 + 8) sv[nf][3] = -1e30f;
            }
        }

        // online softmax, rows r (regs 0,1) and r+8 (regs 2,3)
        float mt0 = -1e30f, mt1 = -1e30f;
#pragma unroll
        for (int nf = 0; nf < 8; nf++) {
            mt0 = fmaxf(mt0, fmaxf(sv[nf][0], sv[nf][1]));
            mt1 = fmaxf(mt1, fmaxf(sv[nf][2], sv[nf][3]));
        }
        mt0 = fmaxf(mt0, __shfl_xor_sync(0xffffffffu, mt0, 1));
        mt0 = fmaxf(mt0, __shfl_xor_sync(0xffffffffu, mt0, 2));
        mt1 = fmaxf(mt1, __shfl_xor_sync(0xffffffffu, mt1, 1));
        mt1 = fmaxf(mt1, __shfl_xor_sync(0xffffffffu, mt1, 2));
        const float mn0 = fmaxf(m0, mt0);
        const float mn1 = fmaxf(m1, mt1);

        float ls0 = 0.0f, ls1 = 0.0f;
#pragma unroll
        for (int nf = 0; nf < 8; nf++) {
            sv[nf][0] = __expf(sv[nf][0] - mn0);
            sv[nf][1] = __expf(sv[nf][1] - mn0);
            sv[nf][2] = __expf(sv[nf][2] - mn1);
            sv[nf][3] = __expf(sv[nf][3] - mn1);
            ls0 += sv[nf][0] + sv[nf][1];
            ls1 += sv[nf][2] + sv[nf][3];
        }
        ls0 += __shfl_xor_sync(0xffffffffu, ls0, 1);
        ls0 += __shfl_xor_sync(0xffffffffu, ls0, 2);
        ls1 += __shfl_xor_sync(0xffffffffu, ls1, 1);
        ls1 += __shfl_xor_sync(0xffffffffu, ls1, 2);

        const float a0 = __expf(m0 - mn0);
        const float a1 = __expf(m1 - mn1);
        l0 = l0 * a0 + ls0;
        l1 = l1 * a1 + ls1;
        m0 = mn0; m1 = mn1;
#pragma unroll
        for (int nf = 0; nf < 8; nf++) {
            o[nf][0] *= a0; o[nf][1] *= a0;
            o[nf][2] *= a1; o[nf][3] *= a1;
        }

        // O += P @ V (split 3-MMA), P fragments straight from accumulators
#pragma unroll
        for (int kp = 0; kp < 4; kp++) {
            uint32_t Ph[4], Pl[4];
            split_pack(sv[2 * kp][0],     sv[2 * kp][1],     Ph[0], Pl[0]);
            split_pack(sv[2 * kp][2],     sv[2 * kp][3],     Ph[1], Pl[1]);
            split_pack(sv[2 * kp + 1][0], sv[2 * kp + 1][1], Ph[2], Pl[2]);
            split_pack(sv[2 * kp + 1][2], sv[2 * kp + 1][3], Ph[3], Pl[3]);
#pragma unroll
            for (int hp = 0; hp < 4; hp++) {
                const uint32_t sw = sw128((uint32_t)(kp * 16 + frow) * 128 + (hp * 16 + koff) * 2);
                uint32_t vhf[4], vlf[4];
                ldsm4t(vhf, sVh + sw);
                ldsm4t(vlf, sVl + sw);
                mma16816(o[hp * 2 + 0], Ph, vhf[0], vhf[1]);
                mma16816(o[hp * 2 + 0], Ph, vlf[0], vlf[1]);
                mma16816(o[hp * 2 + 0], Pl, vhf[0], vhf[1]);
                mma16816(o[hp * 2 + 1], Ph, vhf[2], vhf[3]);
                mma16816(o[hp * 2 + 1], Ph, vlf[2], vlf[3]);
                mma16816(o[hp * 2 + 1], Pl, vhf[2], vhf[3]);
            }
        }
        __syncthreads();
    }

    // epilogue: normalize, split-bf16 scatter to concat [b][s][d]
    const float inv0 = 1.0f / l0;
    const float inv1 = 1.0f / l1;
    const int q0 = qb * 64 + wm + r;
    const int q1 = q0 + 8;
#pragma unroll
    for (int nf = 0; nf < 8; nf++) {
        const int col = h * HD + nf * 8 + cj;
        uint32_t hi, lo;
        split_pack(o[nf][0] * inv0, o[nf][1] * inv0, hi, lo);
        const size_t i0 = ((size_t)b * SEQ + q0) * DM + col;
        *(uint32_t*)(Oh + i0) = hi;
        *(uint32_t*)(Ol + i0) = lo;
        split_pack(o[nf][2] * inv1, o[nf][3] * inv1, hi, lo);
        const size_t i1 = ((size_t)b * SEQ + q1) * DM + col;
        *(uint32_t*)(Oh + i1) = hi;
        *(uint32_t*)(Ol + i1) = lo;
    }
}

// ---------------- launch ----------------
extern "C" void kernel_launch(void* const* d_in, const int* in_sizes, int n_in,
                              void* d_out, int out_size)
{
    const float* x  = (const float*)d_in[0];
    const float* Wq = (const float*)d_in[1];
    const float* Wk = (const float*)d_in[2];
    const float* Wv = (const float*)d_in[3];
    const float* Wo = (const float*)d_in[4];
    float* out = (float*)d_out;

    __nv_bfloat16 *pAh, *pAl, *pWh, *pWl, *pQh, *pQl, *pKh, *pKl, *pVh, *pVl;
    cudaGetSymbolAddress((void**)&pAh, g_Ah);
    cudaGetSymbolAddress((void**)&pAl, g_Al);
    cudaGetSymbolAddress((void**)&pWh, g_Wh);
    cudaGetSymbolAddress((void**)&pWl, g_Wl);
    cudaGetSymbolAddress((void**)&pQh, g_Qh);
    cudaGetSymbolAddress((void**)&pQl, g_Ql);
    cudaGetSymbolAddress((void**)&pKh, g_Kh);
    cudaGetSymbolAddress((void**)&pKl, g_Kl);
    cudaGetSymbolAddress((void**)&pVh, g_Vh);
    cudaGetSymbolAddress((void**)&pVl, g_Vl);

    const int GSMEM = 3 * 32768 + 256;          // 3-stage, K-chunk 32 -> 2 CTAs/SM
    cudaFuncSetAttribute(tgemm_kernel<0>, cudaFuncAttributeMaxDynamicSharedMemorySize, GSMEM);
    cudaFuncSetAttribute(tgemm_kernel<3>, cudaFuncAttributeMaxDynamicSharedMemorySize, GSMEM);

    rope_table_kernel<<<(SEQ * 32 + 255) / 256, 256>>>();

    const int nx4 = BATCH * SEQ * DM / 4;
    const int nw4 = DM * DM / 4;
    split_kernel<<<(nx4 + 255) / 256, 256>>>(x, pAh, pAl, nx4);
    split4_kernel<<<(4 * nw4 + 255) / 256, 256>>>(Wq, Wk, Wv, Wo, pWh, pWl, nw4);

    // fused QKV projections: grid.z selects weight + output
    dim3 qkvgrid(DM / 128, BATCH * SEQ / 128, 3);   // (8, 32, 3)
    tgemm_kernel<3><<<qkvgrid, 256, GSMEM>>>(pAh, pAl, pWh, pWl,
                                             nullptr, pQh, pQl, pKh, pKl, pVh, pVl);

    const int ASMEM = 16384 + 2 * 32768 + 256;  // Q + double-buffered KV
    cudaFuncSetAttribute(attn_hmma_kernel, cudaFuncAttributeMaxDynamicSharedMemorySize, ASMEM);
    attn_hmma_kernel<<<dim3(SEQ / 64, BATCH * NH), 128, ASMEM>>>(pAh, pAl);

    dim3 ogrid(DM / 128, BATCH * SEQ / 128);
    tgemm_kernel<0><<<ogrid, 256, GSMEM>>>(pAh, pAl, pWh + 3 * (size_t)DM * DM, pWl + 3 * (size_t)DM * DM,
                                           out, nullptr, nullptr, nullptr, nullptr, nullptr, nullptr);
}

// round 14
// speedup vs baseline: 1.5818x; 1.4417x over previous
#include <cuda_runtime.h>
#include <cuda_fp16.h>
#include <math.h>
#include <stdint.h>

#define BATCH 2
#define SEQ 2048
#define DM 1024
#define NH 16
#define HD 64

// ---------------- scratch (static device globals; no allocs allowed) ----------------
__device__ float g_cos[SEQ * (HD / 2)];
__device__ float g_sin[SEQ * (HD / 2)];

// fp16 one-sided-split buffers
__device__ __half g_Q [(size_t)BATCH * NH * SEQ * HD];   // rounded side
__device__ __half g_Kh[(size_t)BATCH * NH * SEQ * HD];   // split side
__device__ __half g_Kl[(size_t)BATCH * NH * SEQ * HD];
__device__ __half g_Vh[(size_t)BATCH * NH * SEQ * HD];
__device__ __half g_Vl[(size_t)BATCH * NH * SEQ * HD];

__device__ __half g_A [(size_t)BATCH * SEQ * DM];        // x, later Ctx (rounded side)
__device__ __half g_Wh[4][(size_t)DM * DM];              // weights hi: q,k,v,o (split side)
__device__ __half g_Wl[4][(size_t)DM * DM];              // weights lo

// ---------------- PTX helpers (generic-PTX-safe; sm_80-era features only) ---------
__device__ __forceinline__ uint32_t smem_u32(const void* p) {
    uint32_t a;
    asm("{ .reg .u64 t; cvta.to.shared.u64 t, %1; cvt.u32.u64 %0, t; }" : "=r"(a) : "l"(p));
    return a;
}

__device__ __forceinline__ void sts128(uint32_t addr, uint4 v) {
    asm volatile("st.shared.v4.b32 [%0], {%1,%2,%3,%4};"
                 :: "r"(addr), "r"(v.x), "r"(v.y), "r"(v.z), "r"(v.w) : "memory");
}

__device__ __forceinline__ void cpasync16(uint32_t dst, const void* src) {
    asm volatile("cp.async.cg.shared.global [%0], [%1], 16;" :: "r"(dst), "l"(src) : "memory");
}
__device__ __forceinline__ void cp_commit() {
    asm volatile("cp.async.commit_group;" ::: "memory");
}
template <int N>
__device__ __forceinline__ void cp_wait() {
    asm volatile("cp.async.wait_group %0;" :: "n"(N) : "memory");
}

__device__ __forceinline__ void ldsm4(uint32_t* r, uint32_t addr) {
    asm volatile("ldmatrix.sync.aligned.m8n8.x4.shared.b16 {%0,%1,%2,%3}, [%4];"
                 : "=r"(r[0]), "=r"(r[1]), "=r"(r[2]), "=r"(r[3]) : "r"(addr));
}

__device__ __forceinline__ void ldsm4t(uint32_t* r, uint32_t addr) {
    asm volatile("ldmatrix.sync.aligned.m8n8.x4.trans.shared.b16 {%0,%1,%2,%3}, [%4];"
                 : "=r"(r[0]), "=r"(r[1]), "=r"(r[2]), "=r"(r[3]) : "r"(addr));
}

// fp16 MMA, fp32 accumulate
__device__ __forceinline__ void mma16816(float* c, const uint32_t* a, uint32_t b0, uint32_t b1) {
    asm volatile(
        "mma.sync.aligned.m16n8k16.row.col.f32.f16.f16.f32 "
        "{%0,%1,%2,%3}, {%4,%5,%6,%7}, {%8,%9}, {%0,%1,%2,%3};"
        : "+f"(c[0]), "+f"(c[1]), "+f"(c[2]), "+f"(c[3])
        : "r"(a[0]), "r"(a[1]), "r"(a[2]), "r"(a[3]), "r"(b0), "r"(b1));
}

// pack two fp32 -> half2 (rounded)
__device__ __forceinline__ uint32_t pack_h2(float a, float b) {
    __half2 h = __floats2half2_rn(a, b);
    return *(uint32_t*)&h;
}
// split two fp32 -> half2 hi + half2 lo
__device__ __forceinline__ void split_h2(float a, float b, uint32_t& hi, uint32_t& lo) {
    __half ha = __float2half_rn(a), hb = __float2half_rn(b);
    float ra = a - __half2float(ha), rb = b - __half2float(hb);
    __half2 H = __halves2half2(ha, hb);
    hi = *(uint32_t*)&H;
    lo = pack_h2(ra, rb);
}

// swizzle for 64-byte rows (GEMM tiles)
__device__ __forceinline__ uint32_t sw64(uint32_t off) {
    return off ^ (((off >> 7) & 3u) << 4);
}
// swizzle for 128-byte rows (attention tiles)
__device__ __forceinline__ uint32_t sw128(uint32_t off) {
    return off ^ ((off >> 3) & 0x70u);
}

// ---------------- RoPE table ----------------
__global__ void rope_table_kernel() {
    int idx = blockIdx.x * blockDim.x + threadIdx.x;
    if (idx >= SEQ * (HD / 2)) return;
    int s = idx >> 5;          // HD/2 = 32
    int p = idx & 31;
    float freq = powf(10000.0f, -(float)(2 * p) / (float)HD);
    float ang = (float)s * freq;
    g_cos[idx] = cosf(ang);
    g_sin[idx] = sinf(ang);
}

// ---------------- fp32 -> fp16 round (A side) ----------------
__global__ void round_kernel(const float* __restrict__ x,
                             __half* __restrict__ out, int n4) {
    int i = blockIdx.x * blockDim.x + threadIdx.x;
    if (i >= n4) return;
    float4 v = ((const float4*)x)[i];
    ((uint32_t*)out)[2 * i]     = pack_h2(v.x, v.y);
    ((uint32_t*)out)[2 * i + 1] = pack_h2(v.z, v.w);
}

// all four weight matrices, fp16 hi/lo split, one launch
__global__ void split4_kernel(const float* __restrict__ W0, const float* __restrict__ W1,
                              const float* __restrict__ W2, const float* __restrict__ W3,
                              __half* __restrict__ hi, __half* __restrict__ lo,
                              int n4) {
    int i = blockIdx.x * blockDim.x + threadIdx.x;
    if (i >= 4 * n4) return;
    const int w = i / n4;
    const int j = i - w * n4;
    const float* W = (w == 0) ? W0 : (w == 1) ? W1 : (w == 2) ? W2 : W3;
    float4 v = ((const float4*)W)[j];
    uint32_t h0, l0, h1, l1;
    split_h2(v.x, v.y, h0, l0);
    split_h2(v.z, v.w, h1, l1);
    const size_t base = (size_t)w * (DM * DM / 2);   // in uint32 units
    ((uint32_t*)hi)[base + 2 * j]     = h0;
    ((uint32_t*)hi)[base + 2 * j + 1] = h1;
    ((uint32_t*)lo)[base + 2 * j]     = l0;
    ((uint32_t*)lo)[base + 2 * j + 1] = l1;
}

// ---------------- HMMA one-sided-split fp16 GEMM, 3-stage cp.async ----------------
// C = A(MxK, fp16 rounded) @ (Bh+Bl)(NxK)^T. Block tile 128x128, 8 warps,
// warp tile 32x64, K-chunk 32. 2 MMAs per fragment step.
// MODE 0: row-major fp32 C[M][N]  (O projection)
// MODE 3: fused QKV — z=0: RoPE + rounded Q; z=1: RoPE + split K; z=2: split V.
template <int MODE>
__global__ void __launch_bounds__(256, 2) tgemm_kernel(const __half* __restrict__ A,
                                                       const __half* __restrict__ Bh0,
                                                       const __half* __restrict__ Bl0,
                                                       float* __restrict__ C,
                                                       __half* __restrict__ Qp,
                                                       __half* __restrict__ Kh,
                                                       __half* __restrict__ Kl,
                                                       __half* __restrict__ Vh,
                                                       __half* __restrict__ Vl)
{
    constexpr int Kdim = DM;
    constexpr int NCH = Kdim / 32;         // 32 K-chunks of 32
    constexpr int STAGE = 24576;           // A(8KB) + Bh(8KB) + Bl(8KB)
    extern __shared__ char smem[];
    const int tid = threadIdx.x;
    const int wid = tid >> 5;
    const int l   = tid & 31;
    const int bm = blockIdx.y * 128;
    const int bn = blockIdx.x * 128;

    const __half* Bh = Bh0;
    const __half* Bl = Bl0;
    if (MODE == 3) {
        const size_t woff = (size_t)blockIdx.z * DM * DM;
        Bh = Bh0 + woff;
        Bl = Bl0 + woff;
    }

    const uint32_t tb = (smem_u32(smem) + 127) & ~127u;

    const int wm = (wid >> 1) * 32;
    const int wn = (wid & 1) * 64;

    float acc[2][8][4];
#pragma unroll
    for (int mf = 0; mf < 2; mf++)
#pragma unroll
        for (int nf = 0; nf < 8; nf++)
#pragma unroll
            for (int q = 0; q < 4; q++) acc[mf][nf][q] = 0.0f;

    const int frow = (l & 7) + ((l >> 3) & 1) * 8;
    const int koff = ((l >> 4) & 1) * 8;

    // async-load one K-chunk (32 wide) into a stage
    auto load_chunk = [&](int c, int st) {
        const int k0 = c * 32;
        const uint32_t s0 = tb + st * STAGE;
#pragma unroll
        for (int i = 0; i < 2; i++) {
            const int id = tid + i * 256;
            const int row = id >> 2;            // 0..127
            const int ch = id & 3;              // 0..3 (16B chunks)
            const uint32_t sw = sw64((uint32_t)row * 64 + ch * 16);
            const size_t ga = (size_t)(bm + row) * Kdim + k0 + ch * 8;
            const size_t gb = (size_t)(bn + row) * Kdim + k0 + ch * 8;
            cpasync16(s0 + sw,         A + ga);
            cpasync16(s0 + 8192 + sw,  Bh + gb);
            cpasync16(s0 + 16384 + sw, Bl + gb);
        }
        cp_commit();
    };

    load_chunk(0, 0);
    load_chunk(1, 1);

    for (int c = 0; c < NCH; c++) {
        if (c + 1 < NCH) cp_wait<1>(); else cp_wait<0>();
        __syncthreads();
        if (c + 2 < NCH) load_chunk(c + 2, (c + 2) % 3);

        const uint32_t s0 = tb + (c % 3) * STAGE;
        const uint32_t sA = s0, sBh = s0 + 8192, sBl = s0 + 16384;

        // hoist A fragments for both ks-steps
        uint32_t ahf[2][2][4];   // [ks][mf]
#pragma unroll
        for (int ks = 0; ks < 2; ks++) {
            const int kk = ks * 16 + koff;
#pragma unroll
            for (int mf = 0; mf < 2; mf++) {
                const uint32_t sw = sw64((uint32_t)(wm + mf * 16 + frow) * 64 + kk * 2);
                ldsm4(ahf[ks][mf], sA + sw);
            }
        }

#pragma unroll
        for (int ks = 0; ks < 2; ks++) {
            const int kk = ks * 16 + koff;
#pragma unroll
            for (int np = 0; np < 4; np++) {
                const uint32_t sw = sw64((uint32_t)(wn + np * 16 + frow) * 64 + kk * 2);
                uint32_t bhf[4], blf[4];
                ldsm4(bhf, sBh + sw);
                ldsm4(blf, sBl + sw);
#pragma unroll
                for (int mf = 0; mf < 2; mf++) {
                    mma16816(acc[mf][np * 2 + 0], ahf[ks][mf], bhf[0], bhf[2]);
                    mma16816(acc[mf][np * 2 + 0], ahf[ks][mf], blf[0], blf[2]);
                    mma16816(acc[mf][np * 2 + 1], ahf[ks][mf], bhf[1], bhf[3]);
                    mma16816(acc[mf][np * 2 + 1], ahf[ks][mf], blf[1], blf[3]);
                }
            }
        }
    }

    const int r_lane = l >> 2;
    const int c_lane = (l & 3) * 2;
#pragma unroll
    for (int mf = 0; mf < 2; mf++) {
#pragma unroll
        for (int half = 0; half < 2; half++) {
            const int mrow = bm + wm + mf * 16 + r_lane + half * 8;
            const int b = mrow >> 11;            // SEQ = 2048
            const int s = mrow & (SEQ - 1);
#pragma unroll
            for (int nf = 0; nf < 8; nf++) {
                float e = acc[mf][nf][half * 2 + 0];
                float o = acc[mf][nf][half * 2 + 1];
                const int col = bn + wn + nf * 8 + c_lane;   // even
                if (MODE == 0) {
                    float2 v; v.x = e; v.y = o;
                    *(float2*)(C + (size_t)mrow * DM + col) = v;
                } else {
                    const int h = col >> 6;
                    const int d0 = col & 63;
                    if (blockIdx.z < 2) {        // RoPE for Q, K
                        const int p = d0 >> 1;
                        const float cs = g_cos[s * 32 + p];
                        const float sn = g_sin[s * 32 + p];
                        const float re = e * cs - o * sn;
                        const float ro = e * sn + o * cs;
                        e = re; o = ro;
                    }
                    const size_t idx = (((size_t)b * NH + h) * SEQ + s) * HD + d0;
                    if (blockIdx.z == 0) {
                        *(uint32_t*)(Qp + idx) = pack_h2(e, o);      // Q: rounded only
                    } else {
                        uint32_t hi, lo;
                        split_h2(e, o, hi, lo);
                        __half* Ch = (blockIdx.z == 1) ? Kh : Vh;
                        __half* Cl = (blockIdx.z == 1) ? Kl : Vl;
                        *(uint32_t*)(Ch + idx) = hi;
                        *(uint32_t*)(Cl + idx) = lo;
                    }
                }
            }
        }
    }
}

// ---------------- HMMA flash attention (fp16 one-sided split, causal) -------------
// grid (SEQ/64, BATCH*NH), 128 threads = 4 warps x 16 query rows.
// Q rounded fp16; K,V split. Output: rounded fp16 straight into O-proj A buffer.
__global__ void __launch_bounds__(128) attn_hmma_kernel(__half* __restrict__ Oa)
{
    const int qb = (int)gridDim.x - 1 - (int)blockIdx.x;   // longest-first scheduling
    const int bh = blockIdx.y;
    const int b  = bh >> 4;
    const int h  = bh & 15;
    const size_t base = (size_t)bh * SEQ * HD;

    extern __shared__ char smem[];
    const uint32_t tb  = (smem_u32(smem) + 127) & ~127u;
    const uint32_t sQ  = tb;                       // 64 rows x 128B = 8KB
    const uint32_t kvb = tb + 8192;                // stage s: kvb + s*32768

    const int tid = threadIdx.x;
    const int wid = tid >> 5;
    const int l   = tid & 31;
    const int wm  = wid * 16;
    const int frow = (l & 7) + ((l >> 3) & 1) * 8;
    const int koff = ((l >> 4) & 1) * 8;
    const int r  = l >> 2;
    const int cj = (l & 3) * 2;

    auto load_kv = [&](int jb, int st) {
        const uint32_t s0 = kvb + st * 32768;
#pragma unroll
        for (int i = 0; i < 4; i++) {
            const int id = tid + i * 128;
            const int row = id >> 3;
            const int ch = id & 7;
            const uint32_t sw = sw128((uint32_t)row * 128 + ch * 16);
            const size_t g = base + (size_t)(jb * 64 + row) * HD + ch * 8;
            cpasync16(s0 + sw,         g_Kh + g);
            cpasync16(s0 + 8192 + sw,  g_Kl + g);
            cpasync16(s0 + 16384 + sw, g_Vh + g);
            cpasync16(s0 + 24576 + sw, g_Vl + g);
        }
        cp_commit();
    };

    load_kv(0, 0);

    // load Q tile (64 x 64 fp16) swizzled
#pragma unroll
    for (int i = 0; i < 4; i++) {
        const int id = tid + i * 128;
        const int row = id >> 3;
        const int ch = id & 7;
        const uint32_t sw = sw128((uint32_t)row * 128 + ch * 16);
        const size_t g = base + (size_t)(qb * 64 + row) * HD + ch * 8;
        sts128(sQ + sw, *(const uint4*)(g_Q + g));
    }
    __syncthreads();

    // preload Q fragments (16 rows x 64 k)
    uint32_t qh[4][4];
#pragma unroll
    for (int ks = 0; ks < 4; ks++) {
        const uint32_t sw = sw128((uint32_t)(wm + frow) * 128 + (ks * 16 + koff) * 2);
        ldsm4(qh[ks], sQ + sw);
    }

    float m0 = -1e30f, m1 = -1e30f, l0 = 0.0f, l1 = 0.0f;
    float o[8][4];
#pragma unroll
    for (int nf = 0; nf < 8; nf++)
#pragma unroll
        for (int q = 0; q < 4; q++) o[nf][q] = 0.0f;

    for (int jb = 0; jb <= qb; jb++) {
        if (jb + 1 <= qb) {
            load_kv(jb + 1, (jb + 1) & 1);
            cp_wait<1>();
        } else {
            cp_wait<0>();
        }
        __syncthreads();

        const uint32_t s0 = kvb + (jb & 1) * 32768;
        const uint32_t sKh = s0, sKl = s0 + 8192, sVh = s0 + 16384, sVl = s0 + 24576;

        // S = Q @ (Kh+Kl)^T, 16x64 per warp
        float sv[8][4];
#pragma unroll
        for (int nf = 0; nf < 8; nf++)
#pragma unroll
            for (int q = 0; q < 4; q++) sv[nf][q] = 0.0f;

#pragma unroll
        for (int np = 0; np < 4; np++) {
#pragma unroll
            for (int ks = 0; ks < 4; ks++) {
                const uint32_t sw = sw128((uint32_t)(np * 16 + frow) * 128 + (ks * 16 + koff) * 2);
                uint32_t khf[4], klf[4];
                ldsm4(khf, sKh + sw);
                ldsm4(klf, sKl + sw);
                mma16816(sv[np * 2 + 0], qh[ks], khf[0], khf[2]);
                mma16816(sv[np * 2 + 0], qh[ks], klf[0], klf[2]);
                mma16816(sv[np * 2 + 1], qh[ks], khf[1], khf[3]);
                mma16816(sv[np * 2 + 1], qh[ks], klf[1], klf[3]);
            }
        }

        // scale + causal mask (diagonal tile only)
#pragma unroll
        for (int nf = 0; nf < 8; nf++)
#pragma unroll
            for (int q = 0; q < 4; q++) sv[nf][q] *= 0.125f;

        if (jb == qb) {
#pragma unroll
            for (int nf = 0; nf < 8; nf++) {
                const int k0 = nf * 8 + cj;
                const int q0 = wm + r;
                if (k0     > q0)     sv[nf][0] = -1e30f;
                if (k0 + 1 > q0)     sv[nf][1] = -1e30f;
                if (k0     > q0 + 8) sv[nf][2] = -1e30f;
                if (k0 + 1 > q0 + 8) sv[nf][3] = -1e30f;
            }
        }

        // online softmax, rows r (regs 0,1) and r+8 (regs 2,3)
        float mt0 = -1e30f, mt1 = -1e30f;
#pragma unroll
        for (int nf = 0; nf < 8; nf++) {
            mt0 = fmaxf(mt0, fmaxf(sv[nf][0], sv[nf][1]));
            mt1 = fmaxf(mt1, fmaxf(sv[nf][2], sv[nf][3]));
        }
        mt0 = fmaxf(mt0, __shfl_xor_sync(0xffffffffu, mt0, 1));
        mt0 = fmaxf(mt0, __shfl_xor_sync(0xffffffffu, mt0, 2));
        mt1 = fmaxf(mt1, __shfl_xor_sync(0xffffffffu, mt1, 1));
        mt1 = fmaxf(mt1, __shfl_xor_sync(0xffffffffu, mt1, 2));
        const float mn0 = fmaxf(m0, mt0);
        const float mn1 = fmaxf(m1, mt1);

        float ls0 = 0.0f, ls1 = 0.0f;
#pragma unroll
        for (int nf = 0; nf < 8; nf++) {
            sv[nf][0] = __expf(sv[nf][0] - mn0);
            sv[nf][1] = __expf(sv[nf][1] - mn0);
            sv[nf][2] = __expf(sv[nf][2] - mn1);
            sv[nf][3] = __expf(sv[nf][3] - mn1);
            ls0 += sv[nf][0] + sv[nf][1];
            ls1 += sv[nf][2] + sv[nf][3];
        }
        ls0 += __shfl_xor_sync(0xffffffffu, ls0, 1);
        ls0 += __shfl_xor_sync(0xffffffffu, ls0, 2);
        ls1 += __shfl_xor_sync(0xffffffffu, ls1, 1);
        ls1 += __shfl_xor_sync(0xffffffffu, ls1, 2);

        const float a0 = __expf(m0 - mn0);
        const float a1 = __expf(m1 - mn1);
        l0 = l0 * a0 + ls0;
        l1 = l1 * a1 + ls1;
        m0 = mn0; m1 = mn1;
#pragma unroll
        for (int nf = 0; nf < 8; nf++) {
            o[nf][0] *= a0; o[nf][1] *= a0;
            o[nf][2] *= a1; o[nf][3] *= a1;
        }

        // O += P_fp16 @ (Vh+Vl), P rounded straight from accumulators
#pragma unroll
        for (int kp = 0; kp < 4; kp++) {
            uint32_t Ph[4];
            Ph[0] = pack_h2(sv[2 * kp][0],     sv[2 * kp][1]);
            Ph[1] = pack_h2(sv[2 * kp][2],     sv[2 * kp][3]);
            Ph[2] = pack_h2(sv[2 * kp + 1][0], sv[2 * kp + 1][1]);
            Ph[3] = pack_h2(sv[2 * kp + 1][2], sv[2 * kp + 1][3]);
#pragma unroll
            for (int hp = 0; hp < 4; hp++) {
                const uint32_t sw = sw128((uint32_t)(kp * 16 + frow) * 128 + (hp * 16 + koff) * 2);
                uint32_t vhf[4], vlf[4];
                ldsm4t(vhf, sVh + sw);
                ldsm4t(vlf, sVl + sw);
                mma16816(o[hp * 2 + 0], Ph, vhf[0], vhf[1]);
                mma16816(o[hp * 2 + 0], Ph, vlf[0], vlf[1]);
                mma16816(o[hp * 2 + 1], Ph, vhf[2], vhf[3]);
                mma16816(o[hp * 2 + 1], Ph, vlf[2], vlf[3]);
            }
        }
        __syncthreads();
    }

    // epilogue: normalize, rounded fp16 scatter to concat [b][s][d]
    const float inv0 = 1.0f / l0;
    const float inv1 = 1.0f / l1;
    const int q0 = qb * 64 + wm + r;
    const int q1 = q0 + 8;
#pragma unroll
    for (int nf = 0; nf < 8; nf++) {
        const int col = h * HD + nf * 8 + cj;
        const size_t i0 = ((size_t)b * SEQ + q0) * DM + col;
        const size_t i1 = ((size_t)b * SEQ + q1) * DM + col;
        *(uint32_t*)(Oa + i0) = pack_h2(o[nf][0] * inv0, o[nf][1] * inv0);
        *(uint32_t*)(Oa + i1) = pack_h2(o[nf][2] * inv1, o[nf][3] * inv1);
    }
}

// ---------------- launch ----------------
extern "C" void kernel_launch(void* const* d_in, const int* in_sizes, int n_in,
                              void* d_out, int out_size)
{
    const float* x  = (const float*)d_in[0];
    const float* Wq = (const float*)d_in[1];
    const float* Wk = (const float*)d_in[2];
    const float* Wv = (const float*)d_in[3];
    const float* Wo = (const float*)d_in[4];
    float* out = (float*)d_out;

    __half *pA, *pWh, *pWl, *pQ, *pKh, *pKl, *pVh, *pVl;
    cudaGetSymbolAddress((void**)&pA,  g_A);
    cudaGetSymbolAddress((void**)&pWh, g_Wh);
    cudaGetSymbolAddress((void**)&pWl, g_Wl);
    cudaGetSymbolAddress((void**)&pQ,  g_Q);
    cudaGetSymbolAddress((void**)&pKh, g_Kh);
    cudaGetSymbolAddress((void**)&pKl, g_Kl);
    cudaGetSymbolAddress((void**)&pVh, g_Vh);
    cudaGetSymbolAddress((void**)&pVl, g_Vl);

    const int GSMEM = 3 * 24576 + 256;          // 3 stages x (A + Bh + Bl)
    cudaFuncSetAttribute(tgemm_kernel<0>, cudaFuncAttributeMaxDynamicSharedMemorySize, GSMEM);
    cudaFuncSetAttribute(tgemm_kernel<3>, cudaFuncAttributeMaxDynamicSharedMemorySize, GSMEM);

    rope_table_kernel<<<(SEQ * 32 + 255) / 256, 256>>>();

    const int nx4 = BATCH * SEQ * DM / 4;
    const int nw4 = DM * DM / 4;
    round_kernel<<<(nx4 + 255) / 256, 256>>>(x, pA, nx4);
    split4_kernel<<<(4 * nw4 + 255) / 256, 256>>>(Wq, Wk, Wv, Wo, pWh, pWl, nw4);

    // fused QKV projections: grid.z selects weight + output
    dim3 qkvgrid(DM / 128, BATCH * SEQ / 128, 3);   // (8, 32, 3)
    tgemm_kernel<3><<<qkvgrid, 256, GSMEM>>>(pA, pWh, pWl,
                                             nullptr, pQ, pKh, pKl, pVh, pVl);

    const int ASMEM = 8192 + 2 * 32768 + 256;   // Q + double-buffered KV
    cudaFuncSetAttribute(attn_hmma_kernel, cudaFuncAttributeMaxDynamicSharedMemorySize, ASMEM);
    attn_hmma_kernel<<<dim3(SEQ / 64, BATCH * NH), 128, ASMEM>>>(pA);

    dim3 ogrid(DM / 128, BATCH * SEQ / 128);
    tgemm_kernel<0><<<ogrid, 256, GSMEM>>>(pA, pWh + 3 * (size_t)DM * DM, pWl + 3 * (size_t)DM * DM,
                                           out, nullptr, nullptr, nullptr, nullptr, nullptr);
}

// round 17
// speedup vs baseline: 1.5878x; 1.0038x over previous
#include <cuda_runtime.h>
#include <cuda_fp16.h>
#include <math.h>
#include <stdint.h>

#define BATCH 2
#define SEQ 2048
#define DM 1024
#define NH 16
#define HD 64

// ---------------- scratch (static device globals; no allocs allowed) ----------------
__device__ float g_cos[SEQ * (HD / 2)];
__device__ float g_sin[SEQ * (HD / 2)];

// attention operands, [b][h][s][hd]
__device__ __half g_Qh[(size_t)BATCH * NH * SEQ * HD];   // Q split hi
__device__ __half g_Ql[(size_t)BATCH * NH * SEQ * HD];   // Q split lo
__device__ __half g_K [(size_t)BATCH * NH * SEQ * HD];   // K rounded single
__device__ __half g_V [(size_t)BATCH * NH * SEQ * HD];   // V rounded single

__device__ __half g_A [(size_t)BATCH * SEQ * DM];        // x, later Ctx (rounded side)
__device__ __half g_Wh[4][(size_t)DM * DM];              // weights hi: q,k,v,o (split side)
__device__ __half g_Wl[4][(size_t)DM * DM];              // weights lo

// ---------------- PTX helpers (generic-PTX-safe; sm_80-era features only) ---------
__device__ __forceinline__ uint32_t smem_u32(const void* p) {
    uint32_t a;
    asm("{ .reg .u64 t; cvta.to.shared.u64 t, %1; cvt.u32.u64 %0, t; }" : "=r"(a) : "l"(p));
    return a;
}

__device__ __forceinline__ void sts128(uint32_t addr, uint4 v) {
    asm volatile("st.shared.v4.b32 [%0], {%1,%2,%3,%4};"
                 :: "r"(addr), "r"(v.x), "r"(v.y), "r"(v.z), "r"(v.w) : "memory");
}

__device__ __forceinline__ void cpasync16(uint32_t dst, const void* src) {
    asm volatile("cp.async.cg.shared.global [%0], [%1], 16;" :: "r"(dst), "l"(src) : "memory");
}
__device__ __forceinline__ void cp_commit() {
    asm volatile("cp.async.commit_group;" ::: "memory");
}
template <int N>
__device__ __forceinline__ void cp_wait() {
    asm volatile("cp.async.wait_group %0;" :: "n"(N) : "memory");
}

__device__ __forceinline__ void ldsm4(uint32_t* r, uint32_t addr) {
    asm volatile("ldmatrix.sync.aligned.m8n8.x4.shared.b16 {%0,%1,%2,%3}, [%4];"
                 : "=r"(r[0]), "=r"(r[1]), "=r"(r[2]), "=r"(r[3]) : "r"(addr));
}

__device__ __forceinline__ void ldsm4t(uint32_t* r, uint32_t addr) {
    asm volatile("ldmatrix.sync.aligned.m8n8.x4.trans.shared.b16 {%0,%1,%2,%3}, [%4];"
                 : "=r"(r[0]), "=r"(r[1]), "=r"(r[2]), "=r"(r[3]) : "r"(addr));
}

// fp16 MMA, fp32 accumulate
__device__ __forceinline__ void mma16816(float* c, const uint32_t* a, uint32_t b0, uint32_t b1) {
    asm volatile(
        "mma.sync.aligned.m16n8k16.row.col.f32.f16.f16.f32 "
        "{%0,%1,%2,%3}, {%4,%5,%6,%7}, {%8,%9}, {%0,%1,%2,%3};"
        : "+f"(c[0]), "+f"(c[1]), "+f"(c[2]), "+f"(c[3])
        : "r"(a[0]), "r"(a[1]), "r"(a[2]), "r"(a[3]), "r"(b0), "r"(b1));
}

// pack two fp32 -> half2 (rounded)
__device__ __forceinline__ uint32_t pack_h2(float a, float b) {
    __half2 h = __floats2half2_rn(a, b);
    return *(uint32_t*)&h;
}
// split two fp32 -> half2 hi + half2 lo
__device__ __forceinline__ void split_h2(float a, float b, uint32_t& hi, uint32_t& lo) {
    __half ha = __float2half_rn(a), hb = __float2half_rn(b);
    float ra = a - __half2float(ha), rb = b - __half2float(hb);
    __half2 H = __halves2half2(ha, hb);
    hi = *(uint32_t*)&H;
    lo = pack_h2(ra, rb);
}

// swizzle for 64-byte rows (GEMM tiles)
__device__ __forceinline__ uint32_t sw64(uint32_t off) {
    return off ^ (((off >> 7) & 3u) << 4);
}
// swizzle for 128-byte rows (attention tiles)
__device__ __forceinline__ uint32_t sw128(uint32_t off) {
    return off ^ ((off >> 3) & 0x70u);
}

// ---------------- RoPE table ----------------
__global__ void rope_table_kernel() {
    int idx = blockIdx.x * blockDim.x + threadIdx.x;
    if (idx >= SEQ * (HD / 2)) return;
    int s = idx >> 5;          // HD/2 = 32
    int p = idx & 31;
    float freq = powf(10000.0f, -(float)(2 * p) / (float)HD);
    float ang = (float)s * freq;
    g_cos[idx] = cosf(ang);
    g_sin[idx] = sinf(ang);
}

// ---------------- fp32 -> fp16 round (A side) ----------------
__global__ void round_kernel(const float* __restrict__ x,
                             __half* __restrict__ out, int n4) {
    int i = blockIdx.x * blockDim.x + threadIdx.x;
    if (i >= n4) return;
    float4 v = ((const float4*)x)[i];
    ((uint32_t*)out)[2 * i]     = pack_h2(v.x, v.y);
    ((uint32_t*)out)[2 * i + 1] = pack_h2(v.z, v.w);
}

// all four weight matrices, fp16 hi/lo split, one launch
__global__ void split4_kernel(const float* __restrict__ W0, const float* __restrict__ W1,
                              const float* __restrict__ W2, const float* __restrict__ W3,
                              __half* __restrict__ hi, __half* __restrict__ lo,
                              int n4) {
    int i = blockIdx.x * blockDim.x + threadIdx.x;
    if (i >= 4 * n4) return;
    const int w = i / n4;
    const int j = i - w * n4;
    const float* W = (w == 0) ? W0 : (w == 1) ? W1 : (w == 2) ? W2 : W3;
    float4 v = ((const float4*)W)[j];
    uint32_t h0, l0, h1, l1;
    split_h2(v.x, v.y, h0, l0);
    split_h2(v.z, v.w, h1, l1);
    const size_t base = (size_t)w * (DM * DM / 2);   // in uint32 units
    ((uint32_t*)hi)[base + 2 * j]     = h0;
    ((uint32_t*)hi)[base + 2 * j + 1] = h1;
    ((uint32_t*)lo)[base + 2 * j]     = l0;
    ((uint32_t*)lo)[base + 2 * j + 1] = l1;
}

// ---------------- HMMA one-sided-split fp16 GEMM, 3-stage cp.async ----------------
// C = A(MxK, fp16 rounded) @ (Bh+Bl)(NxK)^T. Block tile 128x128, 8 warps as 2x4,
// warp tile 64x32 (smem-traffic-minimal), K-chunk 32.
// MODE 0: row-major fp32 C[M][N]  (O projection)
// MODE 3: fused QKV — z=0: RoPE + split Q; z=1: RoPE + rounded K; z=2: rounded V.
template <int MODE>
__global__ void __launch_bounds__(256, 2) tgemm_kernel(const __half* __restrict__ A,
                                                       const __half* __restrict__ Bh0,
                                                       const __half* __restrict__ Bl0,
                                                       float* __restrict__ C,
                                                       __half* __restrict__ Qh,
                                                       __half* __restrict__ Ql,
                                                       __half* __restrict__ Kp,
                                                       __half* __restrict__ Vp)
{
    constexpr int Kdim = DM;
    constexpr int NCH = Kdim / 32;         // 32 K-chunks of 32
    constexpr int STAGE = 24576;           // A(8KB) + Bh(8KB) + Bl(8KB)
    extern __shared__ char smem[];
    const int tid = threadIdx.x;
    const int wid = tid >> 5;
    const int l   = tid & 31;
    const int bm = blockIdx.y * 128;
    const int bn = blockIdx.x * 128;

    const __half* Bh = Bh0;
    const __half* Bl = Bl0;
    if (MODE == 3) {
        const size_t woff = (size_t)blockIdx.z * DM * DM;
        Bh = Bh0 + woff;
        Bl = Bl0 + woff;
    }

    const uint32_t tb = (smem_u32(smem) + 127) & ~127u;

    const int wm = (wid >> 2) * 64;        // 2 warp-rows of 64
    const int wn = (wid & 3) * 32;         // 4 warp-cols of 32

    float acc[4][4][4];
#pragma unroll
    for (int mf = 0; mf < 4; mf++)
#pragma unroll
        for (int nf = 0; nf < 4; nf++)
#pragma unroll
            for (int q = 0; q < 4; q++) acc[mf][nf][q] = 0.0f;

    const int frow = (l & 7) + ((l >> 3) & 1) * 8;
    const int koff = ((l >> 4) & 1) * 8;

    // async-load one K-chunk (32 wide) into a stage
    auto load_chunk = [&](int c, int st) {
        const int k0 = c * 32;
        const uint32_t s0 = tb + st * STAGE;
#pragma unroll
        for (int i = 0; i < 2; i++) {
            const int id = tid + i * 256;
            const int row = id >> 2;            // 0..127
            const int ch = id & 3;              // 0..3 (16B chunks)
            const uint32_t sw = sw64((uint32_t)row * 64 + ch * 16);
            const size_t ga = (size_t)(bm + row) * Kdim + k0 + ch * 8;
            const size_t gb = (size_t)(bn + row) * Kdim + k0 + ch * 8;
            cpasync16(s0 + sw,         A + ga);
            cpasync16(s0 + 8192 + sw,  Bh + gb);
            cpasync16(s0 + 16384 + sw, Bl + gb);
        }
        cp_commit();
    };

    load_chunk(0, 0);
    load_chunk(1, 1);

    for (int c = 0; c < NCH; c++) {
        if (c + 1 < NCH) cp_wait<1>(); else cp_wait<0>();
        __syncthreads();
        if (c + 2 < NCH) load_chunk(c + 2, (c + 2) % 3);

        const uint32_t s0 = tb + (c % 3) * STAGE;
        const uint32_t sA = s0, sBh = s0 + 8192, sBl = s0 + 16384;

#pragma unroll
        for (int ks = 0; ks < 2; ks++) {
            const int kk = ks * 16 + koff;
            // A fragments for 64 rows: 4 ldsm4
            uint32_t ahf[4][4];
#pragma unroll
            for (int mf = 0; mf < 4; mf++) {
                const uint32_t sw = sw64((uint32_t)(wm + mf * 16 + frow) * 64 + kk * 2);
                ldsm4(ahf[mf], sA + sw);
            }
#pragma unroll
            for (int np = 0; np < 2; np++) {
                const uint32_t sw = sw64((uint32_t)(wn + np * 16 + frow) * 64 + kk * 2);
                uint32_t bhf[4], blf[4];
                ldsm4(bhf, sBh + sw);
                ldsm4(blf, sBl + sw);
#pragma unroll
                for (int mf = 0; mf < 4; mf++) {
                    mma16816(acc[mf][np * 2 + 0], ahf[mf], bhf[0], bhf[2]);
                    mma16816(acc[mf][np * 2 + 0], ahf[mf], blf[0], blf[2]);
                    mma16816(acc[mf][np * 2 + 1], ahf[mf], bhf[1], bhf[3]);
                    mma16816(acc[mf][np * 2 + 1], ahf[mf], blf[1], blf[3]);
                }
            }
        }
    }

    const int r_lane = l >> 2;
    const int c_lane = (l & 3) * 2;
#pragma unroll
    for (int mf = 0; mf < 4; mf++) {
#pragma unroll
        for (int half = 0; half < 2; half++) {
            const int mrow = bm + wm + mf * 16 + r_lane + half * 8;
            const int b = mrow >> 11;            // SEQ = 2048
            const int s = mrow & (SEQ - 1);
#pragma unroll
            for (int nf = 0; nf < 4; nf++) {
                float e = acc[mf][nf][half * 2 + 0];
                float o = acc[mf][nf][half * 2 + 1];
                const int col = bn + wn + nf * 8 + c_lane;   // even
                if (MODE == 0) {
                    float2 v; v.x = e; v.y = o;
                    *(float2*)(C + (size_t)mrow * DM + col) = v;
                } else {
                    const int h = col >> 6;
                    const int d0 = col & 63;
                    if (blockIdx.z < 2) {        // RoPE for Q, K
                        const int p = d0 >> 1;
                        const float cs = g_cos[s * 32 + p];
                        const float sn = g_sin[s * 32 + p];
                        const float re = e * cs - o * sn;
                        const float ro = e * sn + o * cs;
                        e = re; o = ro;
                    }
                    const size_t idx = (((size_t)b * NH + h) * SEQ + s) * HD + d0;
                    if (blockIdx.z == 0) {       // Q: split hi/lo
                        uint32_t hi, lo;
                        split_h2(e, o, hi, lo);
                        *(uint32_t*)(Qh + idx) = hi;
                        *(uint32_t*)(Ql + idx) = lo;
                    } else {                     // K, V: rounded single
                        __half* Cp = (blockIdx.z == 1) ? Kp : Vp;
                        *(uint32_t*)(Cp + idx) = pack_h2(e, o);
                    }
                }
            }
        }
    }
}

// ---------------- HMMA flash attention (Q,P split; K,V rounded; causal) -----------
// grid (SEQ/64, BATCH*NH), 128 threads = 4 warps x 16 query rows.
__global__ void __launch_bounds__(128) attn_hmma_kernel(__half* __restrict__ Oa)
{
    const int qb = (int)gridDim.x - 1 - (int)blockIdx.x;   // longest-first scheduling
    const int bh = blockIdx.y;
    const int b  = bh >> 4;
    const int h  = bh & 15;
    const size_t base = (size_t)bh * SEQ * HD;

    extern __shared__ char smem[];
    const uint32_t tb  = (smem_u32(smem) + 127) & ~127u;
    const uint32_t sQh = tb;                       // 64 rows x 128B = 8KB
    const uint32_t sQl = tb + 8192;
    const uint32_t kvb = tb + 16384;               // stage s: kvb + s*16384; K at +0, V at +8192

    const int tid = threadIdx.x;
    const int wid = tid >> 5;
    const int l   = tid & 31;
    const int wm  = wid * 16;
    const int frow = (l & 7) + ((l >> 3) & 1) * 8;
    const int koff = ((l >> 4) & 1) * 8;
    const int r  = l >> 2;
    const int cj = (l & 3) * 2;

    auto load_kv = [&](int jb, int st) {
        const uint32_t s0 = kvb + st * 16384;
#pragma unroll
        for (int i = 0; i < 4; i++) {
            const int id = tid + i * 128;
            const int row = id >> 3;
            const int ch = id & 7;
            const uint32_t sw = sw128((uint32_t)row * 128 + ch * 16);
            const size_t g = base + (size_t)(jb * 64 + row) * HD + ch * 8;
            cpasync16(s0 + sw,        g_K + g);
            cpasync16(s0 + 8192 + sw, g_V + g);
        }
        cp_commit();
    };

    load_kv(0, 0);

    // load Q tiles (64 x 64 fp16, hi+lo) swizzled
#pragma unroll
    for (int i = 0; i < 4; i++) {
        const int id = tid + i * 128;
        const int row = id >> 3;
        const int ch = id & 7;
        const uint32_t sw = sw128((uint32_t)row * 128 + ch * 16);
        const size_t g = base + (size_t)(qb * 64 + row) * HD + ch * 8;
        sts128(sQh + sw, *(const uint4*)(g_Qh + g));
        sts128(sQl + sw, *(const uint4*)(g_Ql + g));
    }
    __syncthreads();

    // preload Q fragments (16 rows x 64 k), hi and lo
    uint32_t qh[4][4], ql[4][4];
#pragma unroll
    for (int ks = 0; ks < 4; ks++) {
        const uint32_t sw = sw128((uint32_t)(wm + frow) * 128 + (ks * 16 + koff) * 2);
        ldsm4(qh[ks], sQh + sw);
        ldsm4(ql[ks], sQl + sw);
    }

    float m0 = -1e30f, m1 = -1e30f, l0 = 0.0f, l1 = 0.0f;
    float o[8][4];
#pragma unroll
    for (int nf = 0; nf < 8; nf++)
#pragma unroll
        for (int q = 0; q < 4; q++) o[nf][q] = 0.0f;

    for (int jb = 0; jb <= qb; jb++) {
        if (jb + 1 <= qb) {
            load_kv(jb + 1, (jb + 1) & 1);
            cp_wait<1>();
        } else {
            cp_wait<0>();
        }
        __syncthreads();

        const uint32_t s0 = kvb + (jb & 1) * 16384;
        const uint32_t sK = s0, sV = s0 + 8192;

        // S = (Qh+Ql) @ K^T, 16x64 per warp
        float sv[8][4];
#pragma unroll
        for (int nf = 0; nf < 8; nf++)
#pragma unroll
            for (int q = 0; q < 4; q++) sv[nf][q] = 0.0f;

#pragma unroll
        for (int np = 0; np < 4; np++) {
#pragma unroll
            for (int ks = 0; ks < 4; ks++) {
                const uint32_t sw = sw128((uint32_t)(np * 16 + frow) * 128 + (ks * 16 + koff) * 2);
                uint32_t kf[4];
                ldsm4(kf, sK + sw);
                mma16816(sv[np * 2 + 0], qh[ks], kf[0], kf[2]);
                mma16816(sv[np * 2 + 0], ql[ks], kf[0], kf[2]);
                mma16816(sv[np * 2 + 1], qh[ks], kf[1], kf[3]);
                mma16816(sv[np * 2 + 1], ql[ks], kf[1], kf[3]);
            }
        }

        // scale + causal mask (diagonal tile only)
#pragma unroll
        for (int nf = 0; nf < 8; nf++)
#pragma unroll
            for (int q = 0; q < 4; q++) sv[nf][q] *= 0.125f;

        if (jb == qb) {
#pragma unroll
            for (int nf = 0; nf < 8; nf++) {
                const int k0 = nf * 8 + cj;
                const int q0 = wm + r;
                if (k0     > q0)     sv[nf][0] = -1e30f;
                if (k0 + 1 > q0)     sv[nf][1] = -1e30f;
                if (k0     > q0 + 8) sv[nf][2] = -1e30f;
                if (k0 + 1 > q0 + 8) sv[nf][3] = -1e30f;
            }
        }

        // online softmax, rows r (regs 0,1) and r+8 (regs 2,3)
        float mt0 = -1e30f, mt1 = -1e30f;
#pragma unroll
        for (int nf = 0; nf < 8; nf++) {
            mt0 = fmaxf(mt0, fmaxf(sv[nf][0], sv[nf][1]));
            mt1 = fmaxf(mt1, fmaxf(sv[nf][2], sv[nf][3]));
        }
        mt0 = fmaxf(mt0, __shfl_xor_sync(0xffffffffu, mt0, 1));
        mt0 = fmaxf(mt0, __shfl_xor_sync(0xffffffffu, mt0, 2));
        mt1 = fmaxf(mt1, __shfl_xor_sync(0xffffffffu, mt1, 1));
        mt1 = fmaxf(mt1, __shfl_xor_sync(0xffffffffu, mt1, 2));
        const float mn0 = fmaxf(m0, mt0);
        const float mn1 = fmaxf(m1, mt1);

        float ls0 = 0.0f, ls1 = 0.0f;
#pragma unroll
        for (int nf = 0; nf < 8; nf++) {
            sv[nf][0] = __expf(sv[nf][0] - mn0);
            sv[nf][1] = __expf(sv[nf][1] - mn0);
            sv[nf][2] = __expf(sv[nf][2] - mn1);
            sv[nf][3] = __expf(sv[nf][3] - mn1);
            ls0 += sv[nf][0] + sv[nf][1];
            ls1 += sv[nf][2] + sv[nf][3];
        }
        ls0 += __shfl_xor_sync(0xffffffffu, ls0, 1);
        ls0 += __shfl_xor_sync(0xffffffffu, ls0, 2);
        ls1 += __shfl_xor_sync(0xffffffffu, ls1, 1);
        ls1 += __shfl_xor_sync(0xffffffffu, ls1, 2);

        const float a0 = __expf(m0 - mn0);
        const float a1 = __expf(m1 - mn1);
        l0 = l0 * a0 + ls0;
        l1 = l1 * a1 + ls1;
        m0 = mn0; m1 = mn1;
#pragma unroll
        for (int nf = 0; nf < 8; nf++) {
            o[nf][0] *= a0; o[nf][1] *= a0;
            o[nf][2] *= a1; o[nf][3] *= a1;
        }

        // O += (Ph+Pl) @ V, P split in registers (exact), V rounded single
#pragma unroll
        for (int kp = 0; kp < 4; kp++) {
            uint32_t Ph[4], Pl[4];
            split_h2(sv[2 * kp][0],     sv[2 * kp][1],     Ph[0], Pl[0]);
            split_h2(sv[2 * kp][2],     sv[2 * kp][3],     Ph[1], Pl[1]);
            split_h2(sv[2 * kp + 1][0], sv[2 * kp + 1][1], Ph[2], Pl[2]);
            split_h2(sv[2 * kp + 1][2], sv[2 * kp + 1][3], Ph[3], Pl[3]);
#pragma unroll
            for (int hp = 0; hp < 4; hp++) {
                const uint32_t sw = sw128((uint32_t)(kp * 16 + frow) * 128 + (hp * 16 + koff) * 2);
                uint32_t vf[4];
                ldsm4t(vf, sV + sw);
                mma16816(o[hp * 2 + 0], Ph, vf[0], vf[1]);
                mma16816(o[hp * 2 + 0], Pl, vf[0], vf[1]);
                mma16816(o[hp * 2 + 1], Ph, vf[2], vf[3]);
                mma16816(o[hp * 2 + 1], Pl, vf[2], vf[3]);
            }
        }
        __syncthreads();
    }

    // epilogue: normalize, rounded fp16 scatter to concat [b][s][d]
    const float inv0 = 1.0f / l0;
    const float inv1 = 1.0f / l1;
    const int q0 = qb * 64 + wm + r;
    const int q1 = q0 + 8;
#pragma unroll
    for (int nf = 0; nf < 8; nf++) {
        const int col = h * HD + nf * 8 + cj;
        const size_t i0 = ((size_t)b * SEQ + q0) * DM + col;
        const size_t i1 = ((size_t)b * SEQ + q1) * DM + col;
        *(uint32_t*)(Oa + i0) = pack_h2(o[nf][0] * inv0, o[nf][1] * inv0);
        *(uint32_t*)(Oa + i1) = pack_h2(o[nf][2] * inv1, o[nf][3] * inv1);
    }
}

// ---------------- launch ----------------
extern "C" void kernel_launch(void* const* d_in, const int* in_sizes, int n_in,
                              void* d_out, int out_size)
{
    const float* x  = (const float*)d_in[0];
    const float* Wq = (const float*)d_in[1];
    const float* Wk = (const float*)d_in[2];
    const float* Wv = (const float*)d_in[3];
    const float* Wo = (const float*)d_in[4];
    float* out = (float*)d_out;

    __half *pA, *pWh, *pWl, *pQh, *pQl, *pK, *pV;
    cudaGetSymbolAddress((void**)&pA,  g_A);
    cudaGetSymbolAddress((void**)&pWh, g_Wh);
    cudaGetSymbolAddress((void**)&pWl, g_Wl);
    cudaGetSymbolAddress((void**)&pQh, g_Qh);
    cudaGetSymbolAddress((void**)&pQl, g_Ql);
    cudaGetSymbolAddress((void**)&pK,  g_K);
    cudaGetSymbolAddress((void**)&pV,  g_V);

    const int GSMEM = 3 * 24576 + 256;          // 3 stages x (A + Bh + Bl)
    cudaFuncSetAttribute(tgemm_kernel<0>, cudaFuncAttributeMaxDynamicSharedMemorySize, GSMEM);
    cudaFuncSetAttribute(tgemm_kernel<3>, cudaFuncAttributeMaxDynamicSharedMemorySize, GSMEM);

    rope_table_kernel<<<(SEQ * 32 + 255) / 256, 256>>>();

    const int nx4 = BATCH * SEQ * DM / 4;
    const int nw4 = DM * DM / 4;
    round_kernel<<<(nx4 + 255) / 256, 256>>>(x, pA, nx4);
    split4_kernel<<<(4 * nw4 + 255) / 256, 256>>>(Wq, Wk, Wv, Wo, pWh, pWl, nw4);

    // fused QKV projections: grid.z selects weight + output
    dim3 qkvgrid(DM / 128, BATCH * SEQ / 128, 3);   // (8, 32, 3)
    tgemm_kernel<3><<<qkvgrid, 256, GSMEM>>>(pA, pWh, pWl,
                                             nullptr, pQh, pQl, pK, pV);

    const int ASMEM = 16384 + 2 * 16384 + 256;  // Qh+Ql + double-buffered K,V
    cudaFuncSetAttribute(attn_hmma_kernel, cudaFuncAttributeMaxDynamicSharedMemorySize, ASMEM);
    attn_hmma_kernel<<<dim3(SEQ / 64, BATCH * NH), 128, ASMEM>>>(pA);

    dim3 ogrid(DM / 128, BATCH * SEQ / 128);
    tgemm_kernel<0><<<ogrid, 256, GSMEM>>>(pA, pWh + 3 * (size_t)DM * DM, pWl + 3 * (size_t)DM * DM,
                                           out, nullptr, nullptr, nullptr, nullptr);
}